// round 2
// baseline (speedup 1.0000x reference)
#include <cuda_runtime.h>
#include <math.h>

#define BN 4
#define SS 4096
#define CC 256
#define M_TOT (BN*SS)   // 16384 rows

// ---------------- scratch (static device allocations are allowed) -------------
__device__ float g_xn[(size_t)BN*SS*CC];
__device__ float g_q [(size_t)BN*SS*CC];
__device__ float g_k [(size_t)BN*SS*CC];
__device__ float g_v [(size_t)BN*SS*CC];
__device__ float g_o [(size_t)BN*SS*CC];

// ---------------- LayerNorm: one block per row of 256 ------------------------
__global__ void ln_kernel(const float* __restrict__ x,
                          const float* __restrict__ gamma,
                          const float* __restrict__ beta,
                          float* __restrict__ out) {
    int row = blockIdx.x;
    int t   = threadIdx.x;
    const float* xr = x + (size_t)row * CC;
    float v = xr[t];

    __shared__ float red[8];
    __shared__ float s_mu, s_rstd;

    float s = v;
    #pragma unroll
    for (int o = 16; o; o >>= 1) s += __shfl_xor_sync(0xffffffffu, s, o);
    if ((t & 31) == 0) red[t >> 5] = s;
    __syncthreads();
    if (t == 0) {
        float m = 0.f;
        #pragma unroll
        for (int i = 0; i < 8; i++) m += red[i];
        s_mu = m * (1.0f / CC);
    }
    __syncthreads();
    float mu = s_mu;
    float d  = v - mu;

    s = d * d;
    #pragma unroll
    for (int o = 16; o; o >>= 1) s += __shfl_xor_sync(0xffffffffu, s, o);
    if ((t & 31) == 0) red[t >> 5] = s;
    __syncthreads();
    if (t == 0) {
        float m = 0.f;
        #pragma unroll
        for (int i = 0; i < 8; i++) m += red[i];
        s_rstd = rsqrtf(m * (1.0f / CC) + 1e-3f);
    }
    __syncthreads();

    out[(size_t)row * CC + t] = d * s_rstd * gamma[t] + beta[t];
}

// ---------------- generic GEMM: out[M,256] = A[M,256] @ W[256,256] + bias (+res)
__global__ __launch_bounds__(256) void gemm_kernel(
        const float* __restrict__ A, const float* __restrict__ W,
        const float* __restrict__ bias, const float* __restrict__ res,
        float* __restrict__ out) {
    __shared__ float As[64 * 16];
    __shared__ float Bs[16 * 64];

    int t  = threadIdx.x;
    int tx = t & 15, ty = t >> 4;
    int m0 = blockIdx.y * 64, n0 = blockIdx.x * 64;

    float acc[4][4];
    #pragma unroll
    for (int i = 0; i < 4; i++)
        #pragma unroll
        for (int j = 0; j < 4; j++) acc[i][j] = 0.f;

    for (int kk = 0; kk < CC; kk += 16) {
        int r  = t >> 2, cq = (t & 3) * 4;
        *(float4*)&As[r * 16 + cq] =
            *(const float4*)&A[(size_t)(m0 + r) * CC + kk + cq];
        int kr = t >> 4, c4 = (t & 15) * 4;
        *(float4*)&Bs[kr * 64 + c4] =
            *(const float4*)&W[(size_t)(kk + kr) * CC + n0 + c4];
        __syncthreads();

        #pragma unroll
        for (int k = 0; k < 16; k++) {
            float a0 = As[(ty * 4 + 0) * 16 + k];
            float a1 = As[(ty * 4 + 1) * 16 + k];
            float a2 = As[(ty * 4 + 2) * 16 + k];
            float a3 = As[(ty * 4 + 3) * 16 + k];
            float4 bv = *(float4*)&Bs[k * 64 + tx * 4];
            acc[0][0] = fmaf(a0, bv.x, acc[0][0]); acc[0][1] = fmaf(a0, bv.y, acc[0][1]);
            acc[0][2] = fmaf(a0, bv.z, acc[0][2]); acc[0][3] = fmaf(a0, bv.w, acc[0][3]);
            acc[1][0] = fmaf(a1, bv.x, acc[1][0]); acc[1][1] = fmaf(a1, bv.y, acc[1][1]);
            acc[1][2] = fmaf(a1, bv.z, acc[1][2]); acc[1][3] = fmaf(a1, bv.w, acc[1][3]);
            acc[2][0] = fmaf(a2, bv.x, acc[2][0]); acc[2][1] = fmaf(a2, bv.y, acc[2][1]);
            acc[2][2] = fmaf(a2, bv.z, acc[2][2]); acc[2][3] = fmaf(a2, bv.w, acc[2][3]);
            acc[3][0] = fmaf(a3, bv.x, acc[3][0]); acc[3][1] = fmaf(a3, bv.y, acc[3][1]);
            acc[3][2] = fmaf(a3, bv.z, acc[3][2]); acc[3][3] = fmaf(a3, bv.w, acc[3][3]);
        }
        __syncthreads();
    }

    int col = n0 + tx * 4;
    float4 bb = *(const float4*)&bias[col];
    #pragma unroll
    for (int i = 0; i < 4; i++) {
        int row = m0 + ty * 4 + i;
        float4 o;
        o.x = acc[i][0] + bb.x; o.y = acc[i][1] + bb.y;
        o.z = acc[i][2] + bb.z; o.w = acc[i][3] + bb.w;
        if (res) {
            float4 rr = *(const float4*)&res[(size_t)row * CC + col];
            o.x += rr.x; o.y += rr.y; o.z += rr.z; o.w += rr.w;
        }
        *(float4*)&out[(size_t)row * CC + col] = o;
    }
}

// ---------------- flash attention: Bq=Bk=64, D=256, online softmax ------------
#define FLASH_SMEM_FLOATS (3 * 64 * 256 + 64 * 68)
#define FLASH_SMEM_BYTES  (FLASH_SMEM_FLOATS * 4)

__global__ __launch_bounds__(256) void flash_kernel(
        const float* __restrict__ q, const float* __restrict__ k,
        const float* __restrict__ v, float* __restrict__ o) {
    extern __shared__ float sm[];
    float* Qs = sm;                       // [64][256]
    float* Ks = sm + 64 * 256;            // [64][256], float4-swizzled
    float* Vs = sm + 2 * 64 * 256;        // [64][256]
    float* Ps = sm + 3 * 64 * 256;        // [64][68]

    int b = blockIdx.y, qb = blockIdx.x;
    const float4* qp = (const float4*)(q + ((size_t)b * SS + qb * 64) * CC);
    const float4* kp = (const float4*)(k + (size_t)b * SS * CC);
    const float4* vp = (const float4*)(v + (size_t)b * SS * CC);

    int t = threadIdx.x, tx = t & 15, ty = t >> 4;

    for (int i = t; i < 4096; i += 256) ((float4*)Qs)[i] = qp[i];

    float m[4], l[4];
    float4 O[4][4];
    #pragma unroll
    for (int i = 0; i < 4; i++) {
        m[i] = -1e30f; l[i] = 0.f;
        #pragma unroll
        for (int j = 0; j < 4; j++) O[i][j] = make_float4(0.f, 0.f, 0.f, 0.f);
    }

    for (int kt = 0; kt < 64; kt++) {
        const float4* ksrc = kp + (size_t)kt * 4096;
        const float4* vsrc = vp + (size_t)kt * 4096;
        for (int i = t; i < 4096; i += 256) {
            int r = i >> 6, c4 = i & 63;
            ((float4*)Ks)[r * 64 + (c4 ^ ((r >> 2) & 15))] = ksrc[i];
            ((float4*)Vs)[i] = vsrc[i];
        }
        __syncthreads();

        // ---- scores: S[4][4] = Q(rows ty*4..) . K(cols tx*4..) over D=256 ----
        float s[4][4];
        #pragma unroll
        for (int i = 0; i < 4; i++)
            #pragma unroll
            for (int j = 0; j < 4; j++) s[i][j] = 0.f;

        #pragma unroll 4
        for (int kk = 0; kk < 64; kk++) {       // float4 units of D
            float4 a[4], kb[4];
            #pragma unroll
            for (int i = 0; i < 4; i++)
                a[i] = ((float4*)Qs)[(ty * 4 + i) * 64 + kk];
            #pragma unroll
            for (int j = 0; j < 4; j++) {
                int r = tx * 4 + j;
                kb[j] = ((float4*)Ks)[r * 64 + (kk ^ ((r >> 2) & 15))];
            }
            #pragma unroll
            for (int i = 0; i < 4; i++)
                #pragma unroll
                for (int j = 0; j < 4; j++) {
                    s[i][j] = fmaf(a[i].x, kb[j].x, s[i][j]);
                    s[i][j] = fmaf(a[i].y, kb[j].y, s[i][j]);
                    s[i][j] = fmaf(a[i].z, kb[j].z, s[i][j]);
                    s[i][j] = fmaf(a[i].w, kb[j].w, s[i][j]);
                }
        }

        // ---- online softmax update ----
        const float scale = 0.0625f;  // 256^-0.5
        #pragma unroll
        for (int i = 0; i < 4; i++) {
            float tm = -1e30f;
            #pragma unroll
            for (int j = 0; j < 4; j++) { s[i][j] *= scale; tm = fmaxf(tm, s[i][j]); }
            #pragma unroll
            for (int off = 8; off; off >>= 1)
                tm = fmaxf(tm, __shfl_xor_sync(0xffffffffu, tm, off));
            float mnew = fmaxf(m[i], tm);
            float corr = __expf(m[i] - mnew);
            float rsum = 0.f;
            #pragma unroll
            for (int j = 0; j < 4; j++) {
                float p = __expf(s[i][j] - mnew);
                s[i][j] = p; rsum += p;
            }
            #pragma unroll
            for (int off = 8; off; off >>= 1)
                rsum += __shfl_xor_sync(0xffffffffu, rsum, off);
            l[i] = l[i] * corr + rsum;
            m[i] = mnew;
            #pragma unroll
            for (int j = 0; j < 4; j++) {
                O[i][j].x *= corr; O[i][j].y *= corr;
                O[i][j].z *= corr; O[i][j].w *= corr;
            }
            *(float4*)&Ps[(ty * 4 + i) * 68 + tx * 4] =
                make_float4(s[i][0], s[i][1], s[i][2], s[i][3]);
        }
        __syncthreads();

        // ---- PV: O[64][256] += P[64][64] @ V[64][256] ----
        #pragma unroll 4
        for (int s4 = 0; s4 < 16; s4++) {
            float4 p4[4];
            #pragma unroll
            for (int i = 0; i < 4; i++)
                p4[i] = *(float4*)&Ps[(ty * 4 + i) * 68 + s4 * 4];
            #pragma unroll
            for (int ss = 0; ss < 4; ss++) {
                float4 vv[4];
                #pragma unroll
                for (int jj = 0; jj < 4; jj++)
                    vv[jj] = ((float4*)Vs)[(s4 * 4 + ss) * 64 + jj * 16 + tx];
                #pragma unroll
                for (int i = 0; i < 4; i++) {
                    float p = (ss == 0) ? p4[i].x : (ss == 1) ? p4[i].y
                            : (ss == 2) ? p4[i].z : p4[i].w;
                    #pragma unroll
                    for (int jj = 0; jj < 4; jj++) {
                        O[i][jj].x = fmaf(p, vv[jj].x, O[i][jj].x);
                        O[i][jj].y = fmaf(p, vv[jj].y, O[i][jj].y);
                        O[i][jj].z = fmaf(p, vv[jj].z, O[i][jj].z);
                        O[i][jj].w = fmaf(p, vv[jj].w, O[i][jj].w);
                    }
                }
            }
        }
        __syncthreads();
    }

    // ---- epilogue: divide by l, write O ----
    #pragma unroll
    for (int i = 0; i < 4; i++) {
        float inv = 1.0f / l[i];
        size_t row = (size_t)b * SS + qb * 64 + ty * 4 + i;
        #pragma unroll
        for (int jj = 0; jj < 4; jj++) {
            float4 val;
            val.x = O[i][jj].x * inv; val.y = O[i][jj].y * inv;
            val.z = O[i][jj].z * inv; val.w = O[i][jj].w * inv;
            *(float4*)&o[row * CC + jj * 64 + tx * 4] = val;
        }
    }
}

// ---------------- launcher ----------------------------------------------------
extern "C" void kernel_launch(void* const* d_in, const int* in_sizes, int n_in,
                              void* d_out, int out_size) {
    const float* inputs  = (const float*)d_in[0];
    const float* context = (const float*)d_in[1];
    const float* Wq = (const float*)d_in[2];
    const float* bq = (const float*)d_in[3];
    const float* Wk = (const float*)d_in[4];
    const float* bk = (const float*)d_in[5];
    const float* Wv = (const float*)d_in[6];
    const float* bv = (const float*)d_in[7];
    const float* Wp = (const float*)d_in[8];
    const float* bp = (const float*)d_in[9];
    const float* gamma = (const float*)d_in[10];
    const float* beta  = (const float*)d_in[11];
    float* out = (float*)d_out;

    float *xn, *q, *k, *v, *o;
    cudaGetSymbolAddress((void**)&xn, g_xn);
    cudaGetSymbolAddress((void**)&q,  g_q);
    cudaGetSymbolAddress((void**)&k,  g_k);
    cudaGetSymbolAddress((void**)&v,  g_v);
    cudaGetSymbolAddress((void**)&o,  g_o);

    cudaFuncSetAttribute(flash_kernel,
                         cudaFuncAttributeMaxDynamicSharedMemorySize,
                         FLASH_SMEM_BYTES);

    ln_kernel<<<M_TOT, 256>>>(inputs, gamma, beta, xn);

    dim3 gg(CC / 64, M_TOT / 64);
    gemm_kernel<<<gg, 256>>>(xn,      Wq, bq, nullptr, q);
    gemm_kernel<<<gg, 256>>>(context, Wk, bk, nullptr, k);
    gemm_kernel<<<gg, 256>>>(context, Wv, bv, nullptr, v);

    flash_kernel<<<dim3(SS / 64, BN), 256, FLASH_SMEM_BYTES>>>(q, k, v, o);

    gemm_kernel<<<gg, 256>>>(o, Wp, bp, xn, out);
}

// round 4
// speedup vs baseline: 3.3638x; 3.3638x over previous
#include <cuda_runtime.h>
#include <math.h>
#include <stdint.h>

#define BN 4
#define SS 4096
#define CC 256
#define M_TOT (BN*SS)

__device__ float g_xn[(size_t)BN*SS*CC];
__device__ float g_q [(size_t)BN*SS*CC];
__device__ float g_k [(size_t)BN*SS*CC];
__device__ float g_v [(size_t)BN*SS*CC];
__device__ float g_o [(size_t)BN*SS*CC];

__device__ __forceinline__ uint32_t smem_u32(const void* p){
    uint32_t a; asm("{ .reg .u64 t; cvta.to.shared.u64 t, %1; cvt.u32.u64 %0, t; }":"=r"(a):"l"(p)); return a;
}
__device__ __forceinline__ float rna(float x){
    uint32_t r; asm("cvt.rna.tf32.f32 %0, %1;":"=r"(r):"f"(x)); return __uint_as_float(r);
}
#define MMA(d,a0,a1,a2,a3,b0,b1) \
    asm volatile("mma.sync.aligned.m16n8k8.row.col.f32.tf32.tf32.f32 {%0,%1,%2,%3},{%4,%5,%6,%7},{%8,%9},{%0,%1,%2,%3};" \
        :"+f"(d[0]),"+f"(d[1]),"+f"(d[2]),"+f"(d[3]) \
        :"r"(a0),"r"(a1),"r"(a2),"r"(a3),"r"(b0),"r"(b1))
#define CPA16(off_f, src) asm volatile("cp.async.cg.shared.global [%0], [%1], 16;"::"r"(smb+(uint32_t)((off_f)*4)),"l"(src):"memory")
#define CPC()  asm volatile("cp.async.commit_group;":::"memory")
#define CPW0() asm volatile("cp.async.wait_group 0;":::"memory")
#define CPW1() asm volatile("cp.async.wait_group 1;":::"memory")

// ---------------- LayerNorm ----------------
__global__ void ln_kernel(const float* __restrict__ x, const float* __restrict__ gamma,
                          const float* __restrict__ beta, float* __restrict__ out){
    int row = blockIdx.x, t = threadIdx.x;
    float v = x[(size_t)row*CC + t];
    __shared__ float red[8]; __shared__ float s_mu, s_rs;
    float s = v;
    #pragma unroll
    for(int o=16;o;o>>=1) s += __shfl_xor_sync(~0u,s,o);
    if((t&31)==0) red[t>>5]=s;
    __syncthreads();
    if(t==0){ float m=0; for(int i=0;i<8;i++) m+=red[i]; s_mu=m*(1.f/CC); }
    __syncthreads();
    float d = v - s_mu;
    s = d*d;
    #pragma unroll
    for(int o=16;o;o>>=1) s += __shfl_xor_sync(~0u,s,o);
    if((t&31)==0) red[t>>5]=s;
    __syncthreads();
    if(t==0){ float m=0; for(int i=0;i<8;i++) m+=red[i]; s_rs=rsqrtf(m*(1.f/CC)+1e-3f); }
    __syncthreads();
    out[(size_t)row*CC+t] = d*s_rs*gamma[t] + beta[t];
}

// ---------------- tf32 mma GEMM: out[M,256] = A[M,256]@W[256,256] + bias (+res) ----
// CTA: 256 thr (8 warps x 16 rows), M=128/CTA, N=256, k-chunks of 32.
// smem: As[128][32] xor-swizzled @0 (4096 f); Ws[32][256] xor-swizzled @4096 (8192 f)
#define GEMM_SMEM (12288*4)
__global__ void __launch_bounds__(256,1) gemm_tc(const float* __restrict__ A, const float* __restrict__ W,
        const float* __restrict__ bias, const float* __restrict__ res, float* __restrict__ out, int rnd){
    extern __shared__ float sg[];
    int tid=threadIdx.x, lane=tid&31, wid=tid>>5;
    int g=lane>>2, tig=lane&3;
    int m0 = blockIdx.x*128;

    float acc[32][4];
    #pragma unroll
    for(int i=0;i<32;i++){ acc[i][0]=0.f;acc[i][1]=0.f;acc[i][2]=0.f;acc[i][3]=0.f; }

    // stage chunk 0 (with rna cvt)
    #pragma unroll
    for(int i=0;i<4;i++){ int e=tid+i*256, r=e>>3, c4=e&7;
        float4 x = *(const float4*)&A[(size_t)(m0+r)*CC + c4*4];
        float* d = &sg[r*32 + ((c4*4)^(4*(r&7)))];
        d[0]=rna(x.x); d[1]=rna(x.y); d[2]=rna(x.z); d[3]=rna(x.w); }
    #pragma unroll
    for(int i=0;i<8;i++){ int e=tid+i*256, kr=e>>6, c4=e&63;
        float4 x = *(const float4*)&W[(size_t)kr*CC + c4*4];
        float* d = &sg[4096 + kr*256 + ((c4*4)^(8*(kr&3)))];
        d[0]=rna(x.x); d[1]=rna(x.y); d[2]=rna(x.z); d[3]=rna(x.w); }
    __syncthreads();

    float4 pa[4], pw[8];
    for(int c=0;c<8;c++){
        if(c<7){
            #pragma unroll
            for(int i=0;i<4;i++){ int e=tid+i*256,r=e>>3,c4=e&7;
                pa[i] = *(const float4*)&A[(size_t)(m0+r)*CC + (c+1)*32 + c4*4]; }
            #pragma unroll
            for(int i=0;i<8;i++){ int e=tid+i*256,kr=e>>6,c4=e&63;
                pw[i] = *(const float4*)&W[(size_t)((c+1)*32+kr)*CC + c4*4]; }
        }
        int ar0=(wid*16+g)*32, ar1=(wid*16+g+8)*32;
        #pragma unroll
        for(int kk=0;kk<4;kk++){
            int ca=kk*8+tig, cb=ca+4;
            uint32_t a0=__float_as_uint(sg[ar0 + (ca^(4*g))]);
            uint32_t a1=__float_as_uint(sg[ar1 + (ca^(4*g))]);
            uint32_t a2=__float_as_uint(sg[ar0 + (cb^(4*g))]);
            uint32_t a3=__float_as_uint(sg[ar1 + (cb^(4*g))]);
            int wr0 = 4096 + ca*256, wr1 = 4096 + cb*256;
            #pragma unroll
            for(int nt=0;nt<32;nt++){
                int cx = 8*(nt^tig) + g;
                uint32_t b0=__float_as_uint(sg[wr0 + cx]);
                uint32_t b1=__float_as_uint(sg[wr1 + cx]);
                MMA(acc[nt], a0,a1,a2,a3, b0,b1);
            }
        }
        __syncthreads();
        if(c<7){
            #pragma unroll
            for(int i=0;i<4;i++){ int e=tid+i*256,r=e>>3,c4=e&7;
                float* d=&sg[r*32 + ((c4*4)^(4*(r&7)))];
                d[0]=rna(pa[i].x); d[1]=rna(pa[i].y); d[2]=rna(pa[i].z); d[3]=rna(pa[i].w); }
            #pragma unroll
            for(int i=0;i<8;i++){ int e=tid+i*256,kr=e>>6,c4=e&63;
                float* d=&sg[4096 + kr*256 + ((c4*4)^(8*(kr&3)))];
                d[0]=rna(pw[i].x); d[1]=rna(pw[i].y); d[2]=rna(pw[i].z); d[3]=rna(pw[i].w); }
            __syncthreads();
        }
    }
    int row0 = m0 + wid*16 + g;
    #pragma unroll
    for(int nt=0;nt<32;nt++){
        int col = nt*8 + 2*tig;
        float2 bb = *(const float2*)&bias[col];
        float v0=acc[nt][0]+bb.x, v1=acc[nt][1]+bb.y, v2=acc[nt][2]+bb.x, v3=acc[nt][3]+bb.y;
        if(res){
            float2 x0=*(const float2*)&res[(size_t)row0*CC+col];
            float2 x1=*(const float2*)&res[(size_t)(row0+8)*CC+col];
            v0+=x0.x; v1+=x0.y; v2+=x1.x; v3+=x1.y;
        }
        if(rnd){ v0=rna(v0); v1=rna(v1); v2=rna(v2); v3=rna(v3); }
        float2 w0={v0,v1}, w1={v2,v3};
        *(float2*)&out[(size_t)row0*CC+col] = w0;
        *(float2*)&out[(size_t)(row0+8)*CC+col] = w1;
    }
}

// ---------------- tf32 mma flash attention ----------------
// Bq=64 rows/CTA, 8 warps: pair p=wid>>1 owns rows p*16..+15; half h=wid&1 splits keys/channels.
// smem floats: Q @0 (16384); K @16384 (2x8192); V @32768 (2x8192); P @49152 (4x576); ls @51456 (128)
#define FL_SMEM (51584*4)
__global__ void __launch_bounds__(256,1) flash_tc(const float* __restrict__ q,
        const float* __restrict__ k, const float* __restrict__ v, float* __restrict__ o){
    extern __shared__ float sm[];
    const uint32_t smb = smem_u32(sm);
    int tid=threadIdx.x, lane=tid&31, wid=tid>>5;
    int g=lane>>2, tig=lane&3, p=wid>>1, h=wid&1;
    int b=blockIdx.y, qb=blockIdx.x;
    const float* qg = q + ((size_t)b*SS + (size_t)qb*64)*CC;
    const float* kg = k + (size_t)b*SS*CC;
    const float* vg = v + (size_t)b*SS*CC;

    // stage Q + K0/V0 via cp.async (inputs pre-rounded to tf32 by gemm_tc rnd=1)
    #pragma unroll
    for(int i=0;i<16;i++){ int e=tid+i*256, r=e>>6, c4=e&63;
        CPA16(r*256 + ((c4*4)^(4*(r&7))), qg + e*4); }
    #pragma unroll
    for(int i=0;i<8;i++){ int e=tid+i*256, ky=e>>6, c4=e&63;
        CPA16(16384 + ky*256 + ((c4*4)^(4*(ky&7))), kg + e*4);
        CPA16(32768 + ky*256 + ((c4*4)^(8*(ky&3))), vg + e*4); }
    CPC(); CPW0(); __syncthreads();

    float acc[16][4];
    #pragma unroll
    for(int i=0;i<16;i++){ acc[i][0]=0.f;acc[i][1]=0.f;acc[i][2]=0.f;acc[i][3]=0.f; }
    float l0=0.f, l1=0.f;
    int arow0 = (p*16+g)*256, arow1 = (p*16+g+8)*256;
    int pb = 49152 + p*576;

    for(int t=0;t<128;t++){
        int buf=t&1;
        if(t<127){
            const float* kt = kg + (size_t)(t+1)*8192;
            const float* vt = vg + (size_t)(t+1)*8192;
            int bo = (buf^1)*8192;
            #pragma unroll
            for(int i=0;i<8;i++){ int e=tid+i*256, ky=e>>6, c4=e&63;
                CPA16(16384 + bo + ky*256 + ((c4*4)^(4*(ky&7))), kt + e*4);
                CPA16(32768 + bo + ky*256 + ((c4*4)^(8*(ky&3))), vt + e*4); }
            CPC(); CPW1();
        } else CPW0();
        __syncthreads();

        // QK: S[16 rows][16 keys of this half] = 2 n-tiles
        float s0[4]={0.f,0.f,0.f,0.f}, s1[4]={0.f,0.f,0.f,0.f};
        int kb = 16384 + buf*8192;
        int key0r = kb + (h*16+g)*256, key1r = kb + (h*16+8+g)*256;
        #pragma unroll
        for(int kk=0;kk<32;kk++){
            int ca=kk*8+tig, cb=ca+4;
            int xa = ca^(4*g), xb = cb^(4*g);
            uint32_t a0=__float_as_uint(sm[arow0+xa]);
            uint32_t a1=__float_as_uint(sm[arow1+xa]);
            uint32_t a2=__float_as_uint(sm[arow0+xb]);
            uint32_t a3=__float_as_uint(sm[arow1+xb]);
            uint32_t b0=__float_as_uint(sm[key0r+xa]);
            uint32_t b1=__float_as_uint(sm[key0r+xb]);
            MMA(s0, a0,a1,a2,a3, b0,b1);
            b0=__float_as_uint(sm[key1r+xa]);
            b1=__float_as_uint(sm[key1r+xb]);
            MMA(s1, a0,a1,a2,a3, b0,b1);
        }
        // softmax (no max: |s*scale| <= ~16, exp can't overflow fp32)
        {
            float e0=rna(__expf(s0[0]*0.0625f)), e1=rna(__expf(s0[1]*0.0625f));
            float e2=rna(__expf(s0[2]*0.0625f)), e3=rna(__expf(s0[3]*0.0625f));
            l0+=e0+e1; l1+=e2+e3;
            int col = h*16 + 2*tig;
            float2 w0={e0,e1}, w1={e2,e3};
            *(float2*)&sm[pb + g*36 + col] = w0;
            *(float2*)&sm[pb + (g+8)*36 + col] = w1;
            e0=rna(__expf(s1[0]*0.0625f)); e1=rna(__expf(s1[1]*0.0625f));
            e2=rna(__expf(s1[2]*0.0625f)); e3=rna(__expf(s1[3]*0.0625f));
            l0+=e0+e1; l1+=e2+e3;
            col += 8;
            float2 w2={e0,e1}, w3={e2,e3};
            *(float2*)&sm[pb + g*36 + col] = w2;
            *(float2*)&sm[pb + (g+8)*36 + col] = w3;
        }
        __syncthreads();
        // PV: O[16][128 of this half] += P[16][32] @ V[32][256-half]
        int vb = 32768 + buf*8192;
        #pragma unroll
        for(int ks=0;ks<4;ks++){
            int ka = ks*8+tig;
            uint32_t a0=__float_as_uint(sm[pb + g*36 + ka]);
            uint32_t a1=__float_as_uint(sm[pb + (g+8)*36 + ka]);
            uint32_t a2=__float_as_uint(sm[pb + g*36 + ka+4]);
            uint32_t a3=__float_as_uint(sm[pb + (g+8)*36 + ka+4]);
            int kr0 = vb + ka*256, kr1 = vb + (ka+4)*256;
            #pragma unroll
            for(int nt=0;nt<16;nt++){
                int cx = h*128 + 8*(nt^tig) + g;
                uint32_t b0=__float_as_uint(sm[kr0 + cx]);
                uint32_t b1=__float_as_uint(sm[kr1 + cx]);
                MMA(acc[nt], a0,a1,a2,a3, b0,b1);
            }
        }
        __syncthreads();
    }
    // combine l: across tig, then across halves via smem
    l0 += __shfl_xor_sync(~0u,l0,1); l0 += __shfl_xor_sync(~0u,l0,2);
    l1 += __shfl_xor_sync(~0u,l1,1); l1 += __shfl_xor_sync(~0u,l1,2);
    if(tig==0){
        sm[51456 + (p*16+g)*2 + h]   = l0;
        sm[51456 + (p*16+g+8)*2 + h] = l1;
    }
    __syncthreads();
    float inv0 = 1.f/(sm[51456+(p*16+g)*2]   + sm[51456+(p*16+g)*2+1]);
    float inv1 = 1.f/(sm[51456+(p*16+g+8)*2] + sm[51456+(p*16+g+8)*2+1]);
    float* o0 = o + ((size_t)b*SS + (size_t)qb*64 + p*16 + g)*CC;
    float* o1 = o0 + 8*CC;
    #pragma unroll
    for(int nt=0;nt<16;nt++){
        int col = h*128 + nt*8 + 2*tig;
        float2 w0 = { rna(acc[nt][0]*inv0), rna(acc[nt][1]*inv0) };
        float2 w1 = { rna(acc[nt][2]*inv1), rna(acc[nt][3]*inv1) };
        *(float2*)&o0[col]=w0; *(float2*)&o1[col]=w1;
    }
}

// ---------------- launcher ----------------
extern "C" void kernel_launch(void* const* d_in, const int* in_sizes, int n_in,
                              void* d_out, int out_size){
    const float* inputs  = (const float*)d_in[0];
    const float* context = (const float*)d_in[1];
    const float* Wq=(const float*)d_in[2];  const float* bq=(const float*)d_in[3];
    const float* Wk=(const float*)d_in[4];  const float* bk=(const float*)d_in[5];
    const float* Wv=(const float*)d_in[6];  const float* bv=(const float*)d_in[7];
    const float* Wp=(const float*)d_in[8];  const float* bp=(const float*)d_in[9];
    const float* gamma=(const float*)d_in[10]; const float* beta=(const float*)d_in[11];
    float* out=(float*)d_out;
    float *xn,*q,*k,*v,*o;
    cudaGetSymbolAddress((void**)&xn,g_xn); cudaGetSymbolAddress((void**)&q,g_q);
    cudaGetSymbolAddress((void**)&k,g_k);   cudaGetSymbolAddress((void**)&v,g_v);
    cudaGetSymbolAddress((void**)&o,g_o);
    cudaFuncSetAttribute(flash_tc, cudaFuncAttributeMaxDynamicSharedMemorySize, FL_SMEM);
    cudaFuncSetAttribute(gemm_tc,  cudaFuncAttributeMaxDynamicSharedMemorySize, GEMM_SMEM);

    ln_kernel<<<M_TOT,256>>>(inputs,gamma,beta,xn);
    gemm_tc<<<M_TOT/128,256,GEMM_SMEM>>>(xn,      Wq,bq,nullptr,q, 1);
    gemm_tc<<<M_TOT/128,256,GEMM_SMEM>>>(context, Wk,bk,nullptr,k, 1);
    gemm_tc<<<M_TOT/128,256,GEMM_SMEM>>>(context, Wv,bv,nullptr,v, 1);
    flash_tc<<<dim3(SS/64, BN), 256, FL_SMEM>>>(q,k,v,o);
    gemm_tc<<<M_TOT/128,256,GEMM_SMEM>>>(o, Wp,bp,xn,out, 0);
}

// round 5
// speedup vs baseline: 7.3577x; 2.1873x over previous
#include <cuda_runtime.h>
#include <cuda_fp16.h>
#include <math.h>
#include <stdint.h>

#define BN 4
#define SS 4096
#define CC 256
#define M_TOT (BN*SS)

__device__ float  g_xn [(size_t)BN*SS*CC];
__device__ __half g_q16[(size_t)BN*SS*CC];
__device__ __half g_k16[(size_t)BN*SS*CC];
__device__ __half g_v16[(size_t)BN*SS*CC];
__device__ __half g_o16[(size_t)BN*SS*CC];

__device__ __forceinline__ uint32_t smem_u32(const void* p){
    uint32_t a; asm("{ .reg .u64 t; cvta.to.shared.u64 t, %1; cvt.u32.u64 %0, t; }":"=r"(a):"l"(p)); return a;
}
#define MMAH(d,a0,a1,a2,a3,b0,b1) \
    asm volatile("mma.sync.aligned.m16n8k16.row.col.f32.f16.f16.f32 {%0,%1,%2,%3},{%4,%5,%6,%7},{%8,%9},{%0,%1,%2,%3};" \
        :"+f"(d[0]),"+f"(d[1]),"+f"(d[2]),"+f"(d[3]) \
        :"r"(a0),"r"(a1),"r"(a2),"r"(a3),"r"(b0),"r"(b1))
#define LDSM4(r0,r1,r2,r3,a) asm volatile("ldmatrix.sync.aligned.m8n8.x4.shared.b16 {%0,%1,%2,%3},[%4];" \
        :"=r"(r0),"=r"(r1),"=r"(r2),"=r"(r3):"r"(a))
#define LDSM2(r0,r1,a) asm volatile("ldmatrix.sync.aligned.m8n8.x2.shared.b16 {%0,%1},[%2];" \
        :"=r"(r0),"=r"(r1):"r"(a))
#define LDSM2T(r0,r1,a) asm volatile("ldmatrix.sync.aligned.m8n8.x2.trans.shared.b16 {%0,%1},[%2];" \
        :"=r"(r0),"=r"(r1):"r"(a))
#define CPAH(off_h, src) asm volatile("cp.async.cg.shared.global [%0], [%1], 16;"::"r"(smb+(uint32_t)((off_h)*2)),"l"(src):"memory")
#define CPC()  asm volatile("cp.async.commit_group;":::"memory")
#define CPW0() asm volatile("cp.async.wait_group 0;":::"memory")
#define CPW1() asm volatile("cp.async.wait_group 1;":::"memory")
__device__ __forceinline__ uint32_t h2u(__half2 x){ return *(uint32_t*)&x; }

// ---------------- LayerNorm ----------------
__global__ void ln_kernel(const float* __restrict__ x, const float* __restrict__ gamma,
                          const float* __restrict__ beta, float* __restrict__ out){
    int row = blockIdx.x, t = threadIdx.x;
    float v = x[(size_t)row*CC + t];
    __shared__ float red[8]; __shared__ float s_mu, s_rs;
    float s = v;
    #pragma unroll
    for(int o=16;o;o>>=1) s += __shfl_xor_sync(~0u,s,o);
    if((t&31)==0) red[t>>5]=s;
    __syncthreads();
    if(t==0){ float m=0; for(int i=0;i<8;i++) m+=red[i]; s_mu=m*(1.f/CC); }
    __syncthreads();
    float d = v - s_mu;
    s = d*d;
    #pragma unroll
    for(int o=16;o;o>>=1) s += __shfl_xor_sync(~0u,s,o);
    if((t&31)==0) red[t>>5]=s;
    __syncthreads();
    if(t==0){ float m=0; for(int i=0;i<8;i++) m+=red[i]; s_rs=rsqrtf(m*(1.f/CC)+1e-3f); }
    __syncthreads();
    out[(size_t)row*CC+t] = d*s_rs*gamma[t] + beta[t];
}

// ---------------- fp16 mma GEMM: out = A[128rows,256]@W[256,256] + bias (+res) ----
#define GW 32768
#define G_BYTES 196608
__global__ void __launch_bounds__(256,1) gemm_h(const float* __restrict__ A32,
        const __half* __restrict__ A16, const float* __restrict__ W,
        const float* __restrict__ bias, const float* __restrict__ res,
        float* __restrict__ out32, __half* __restrict__ out16){
    extern __shared__ __half sh[];
    const uint32_t smb = smem_u32(sh);
    int tid=threadIdx.x, lane=tid&31, wid=tid>>5;
    int g=lane>>2, tig=lane&3;
    int m0 = blockIdx.x*128;
    // stage W (fp32 -> fp16, chunk-swizzled [k][n])
    #pragma unroll
    for(int i=0;i<32;i++){ int c=tid+i*256, kr=c>>5, ch=c&31;
        const float4* s=(const float4*)(W + (size_t)kr*256 + ch*8);
        float4 u=s[0], w=s[1];
        uint4 pk = make_uint4(h2u(__floats2half2_rn(u.x,u.y)), h2u(__floats2half2_rn(u.z,u.w)),
                              h2u(__floats2half2_rn(w.x,w.y)), h2u(__floats2half2_rn(w.z,w.w)));
        *(uint4*)(sh + GW + kr*256 + ((ch^(kr&7))<<3)) = pk; }
    // stage A
    if(A32){
        #pragma unroll
        for(int i=0;i<16;i++){ int c=tid+i*256, r=c>>5, ch=c&31;
            const float4* s=(const float4*)(A32 + (size_t)(m0+r)*256 + ch*8);
            float4 u=s[0], w=s[1];
            uint4 pk = make_uint4(h2u(__floats2half2_rn(u.x,u.y)), h2u(__floats2half2_rn(u.z,u.w)),
                                  h2u(__floats2half2_rn(w.x,w.y)), h2u(__floats2half2_rn(w.z,w.w)));
            *(uint4*)(sh + r*256 + ((ch^(r&7))<<3)) = pk; }
    } else {
        #pragma unroll
        for(int i=0;i<16;i++){ int c=tid+i*256, r=c>>5, ch=c&31;
            uint4 u = *(const uint4*)(A16 + (size_t)(m0+r)*256 + ch*8);
            *(uint4*)(sh + r*256 + ((ch^(r&7))<<3)) = u; }
    }
    __syncthreads();

    float acc[32][4];
    #pragma unroll
    for(int i=0;i<32;i++){ acc[i][0]=0.f;acc[i][1]=0.f;acc[i][2]=0.f;acc[i][3]=0.f; }
    const int rq = wid*16 + (lane&7) + (lane&8);
    const uint32_t aqb = smb + (uint32_t)rq*512; const int rq7=rq&7;
    const int sel=(lane>>3)&1, hi=(lane>>4)&1, r7=lane&7;
    #pragma unroll
    for(int ki=0;ki<16;ki++){
        uint32_t a0,a1,a2,a3;
        LDSM4(a0,a1,a2,a3, aqb + (uint32_t)(((2*ki+hi)^rq7)<<4));
        int krow = ki*16 + sel*8 + r7;
        uint32_t wr = smb + (uint32_t)(GW + krow*256)*2; int xw=krow&7;
        #pragma unroll
        for(int nt=0;nt<32;nt++){
            uint32_t b0,b1;
            LDSM2T(b0,b1, wr + (uint32_t)((nt^xw)<<4));
            MMAH(acc[nt], a0,a1,a2,a3, b0,b1);
        }
    }
    int row0 = m0 + wid*16 + g;
    #pragma unroll
    for(int nt=0;nt<32;nt++){
        int col = nt*8 + 2*tig;
        float2 bb = *(const float2*)&bias[col];
        float v0=acc[nt][0]+bb.x, v1=acc[nt][1]+bb.y, v2=acc[nt][2]+bb.x, v3=acc[nt][3]+bb.y;
        if(out32){
            float2 x0=*(const float2*)&res[(size_t)row0*256+col];
            float2 x1=*(const float2*)&res[(size_t)(row0+8)*256+col];
            float2 w0={v0+x0.x, v1+x0.y}, w1={v2+x1.x, v3+x1.y};
            *(float2*)&out32[(size_t)row0*256+col]=w0;
            *(float2*)&out32[(size_t)(row0+8)*256+col]=w1;
        } else {
            *(__half2*)(out16 + (size_t)row0*256+col)     = __floats2half2_rn(v0,v1);
            *(__half2*)(out16 + (size_t)(row0+8)*256+col) = __floats2half2_rn(v2,v3);
        }
    }
}

// ---------------- fp16 mma flash attention ----------------
// smem halfs: Q@0 (64x256=16384); K@16384 (2x32x256); V@32768 (2x32x256);
// P@49152 (4 pairs x 16rows x pitch56); l floats @half-off 52736. Total 105984 B.
#define FK 16384
#define FV 32768
#define FP 49152
#define FLS 52736
#define FL_BYTES 105984
__global__ void __launch_bounds__(256,2) flash_h(const __half* __restrict__ q,
        const __half* __restrict__ k, const __half* __restrict__ v, __half* __restrict__ o){
    extern __shared__ __half sh[];
    const uint32_t smb = smem_u32(sh);
    int tid=threadIdx.x, lane=tid&31, wid=tid>>5;
    int g=lane>>2, tig=lane&3, p=wid>>1, h=wid&1;
    int b=blockIdx.y, qb=blockIdx.x;
    const __half* qg = q + ((size_t)b*SS + (size_t)qb*64)*CC;
    const __half* kg = k + (size_t)b*SS*CC;
    const __half* vg = v + (size_t)b*SS*CC;

    // stage Q + K0 + V0
    #pragma unroll
    for(int i=0;i<8;i++){ int c=tid+i*256, r=c>>5, ch=c&31;
        CPAH(r*256 + ((ch^(r&7))<<3), qg + (size_t)c*8); }
    #pragma unroll
    for(int i=0;i<4;i++){ int c=tid+i*256, r=c>>5, ch=c&31;
        int sw = r*256 + ((ch^(r&7))<<3);
        CPAH(FK + sw, kg + (size_t)c*8);
        CPAH(FV + sw, vg + (size_t)c*8); }
    CPC();

    float acc[16][4];
    #pragma unroll
    for(int i=0;i<16;i++){ acc[i][0]=0.f;acc[i][1]=0.f;acc[i][2]=0.f;acc[i][3]=0.f; }
    float l0=0.f, l1=0.f;
    const int rq = p*16 + (lane&7) + (lane&8);
    const uint32_t aqb = smb + (uint32_t)rq*512; const int rq7=rq&7;
    const int sel=(lane>>3)&1, hi=(lane>>4)&1, r7=lane&7;
    const int kr0 = h*16 + r7, kr1 = kr0+8;
    const int x0=kr0&7, x1=kr1&7;
    const uint32_t apb = smb + (uint32_t)(FP + p*896 + ((lane&7)+(lane&8))*56)*2;
    __half2* psm = (__half2*)(sh + FP + p*896);

    for(int t=0;t<128;t++){
        int buf=t&1;
        if(t<127){
            const __half* kt = kg + (size_t)(t+1)*8192;
            const __half* vt = vg + (size_t)(t+1)*8192;
            int bo = (buf^1)*8192;
            #pragma unroll
            for(int i=0;i<4;i++){ int c=tid+i*256, r=c>>5, ch=c&31;
                int sw = r*256 + ((ch^(r&7))<<3);
                CPAH(FK + bo + sw, kt + (size_t)c*8);
                CPAH(FV + bo + sw, vt + (size_t)c*8); }
            CPC(); CPW1();
        } else CPW0();
        __syncthreads();
        uint32_t kbb = smb + (uint32_t)(FK + buf*8192)*2;
        uint32_t vbb = smb + (uint32_t)(FV + buf*8192)*2;
        uint32_t ka0 = kbb + (uint32_t)kr0*512, ka1 = kbb + (uint32_t)kr1*512;
        float s0[4]={0.f,0.f,0.f,0.f}, s1[4]={0.f,0.f,0.f,0.f};
        #pragma unroll
        for(int ki=0;ki<16;ki++){
            uint32_t a0,a1,a2,a3,b0,b1,c0,c1;
            LDSM4(a0,a1,a2,a3, aqb + (uint32_t)(((2*ki+hi)^rq7)<<4));
            LDSM2(b0,b1, ka0 + (uint32_t)(((2*ki+sel)^x0)<<4));
            LDSM2(c0,c1, ka1 + (uint32_t)(((2*ki+sel)^x1)<<4));
            MMAH(s0, a0,a1,a2,a3, b0,b1);
            MMAH(s1, a0,a1,a2,a3, c0,c1);
        }
        const float SC=0.0625f;
        float e00=__expf(s0[0]*SC), e01=__expf(s0[1]*SC), e02=__expf(s0[2]*SC), e03=__expf(s0[3]*SC);
        float f00=__expf(s1[0]*SC), f01=__expf(s1[1]*SC), f02=__expf(s1[2]*SC), f03=__expf(s1[3]*SC);
        l0 += e00+e01+f00+f01; l1 += e02+e03+f02+f03;
        int pc = g*28 + h*8 + tig;
        psm[pc]     = __floats2half2_rn(e00,e01);
        psm[pc+224] = __floats2half2_rn(e02,e03);
        psm[pc+4]   = __floats2half2_rn(f00,f01);
        psm[pc+228] = __floats2half2_rn(f02,f03);
        asm volatile("bar.sync %0, 64;" :: "r"(1+p) : "memory");
        #pragma unroll
        for(int kp=0;kp<2;kp++){
            uint32_t pa0,pa1,pa2,pa3;
            LDSM4(pa0,pa1,pa2,pa3, apb + (uint32_t)((2*kp+hi)<<4));
            int krow = kp*16 + sel*8 + r7;
            uint32_t vr = vbb + (uint32_t)krow*512; int xv=krow&7;
            #pragma unroll
            for(int nt=0;nt<16;nt++){
                uint32_t b0,b1;
                LDSM2T(b0,b1, vr + (uint32_t)(((h*16+nt)^xv)<<4));
                MMAH(acc[nt], pa0,pa1,pa2,pa3, b0,b1);
            }
        }
        __syncthreads();
    }
    l0 += __shfl_xor_sync(~0u,l0,1); l0 += __shfl_xor_sync(~0u,l0,2);
    l1 += __shfl_xor_sync(~0u,l1,1); l1 += __shfl_xor_sync(~0u,l1,2);
    float* lf = (float*)(sh + FLS);
    if(tig==0){ lf[(p*16+g)*2+h]=l0; lf[(p*16+8+g)*2+h]=l1; }
    __syncthreads();
    float inv0 = 1.f/(lf[(p*16+g)*2]   + lf[(p*16+g)*2+1]);
    float inv1 = 1.f/(lf[(p*16+8+g)*2] + lf[(p*16+8+g)*2+1]);
    __half* o0 = o + ((size_t)b*SS + (size_t)qb*64 + p*16 + g)*CC;
    __half* o1 = o0 + 8*CC;
    #pragma unroll
    for(int nt=0;nt<16;nt++){
        int col = h*128 + nt*8 + 2*tig;
        *(__half2*)(o0+col) = __floats2half2_rn(acc[nt][0]*inv0, acc[nt][1]*inv0);
        *(__half2*)(o1+col) = __floats2half2_rn(acc[nt][2]*inv1, acc[nt][3]*inv1);
    }
}

// ---------------- launcher ----------------
extern "C" void kernel_launch(void* const* d_in, const int* in_sizes, int n_in,
                              void* d_out, int out_size){
    const float* inputs  = (const float*)d_in[0];
    const float* context = (const float*)d_in[1];
    const float* Wq=(const float*)d_in[2];  const float* bq=(const float*)d_in[3];
    const float* Wk=(const float*)d_in[4];  const float* bk=(const float*)d_in[5];
    const float* Wv=(const float*)d_in[6];  const float* bv=(const float*)d_in[7];
    const float* Wp=(const float*)d_in[8];  const float* bp=(const float*)d_in[9];
    const float* gamma=(const float*)d_in[10]; const float* beta=(const float*)d_in[11];
    float* out=(float*)d_out;
    float *xn; __half *q16,*k16,*v16,*o16;
    cudaGetSymbolAddress((void**)&xn,g_xn);
    cudaGetSymbolAddress((void**)&q16,g_q16); cudaGetSymbolAddress((void**)&k16,g_k16);
    cudaGetSymbolAddress((void**)&v16,g_v16); cudaGetSymbolAddress((void**)&o16,g_o16);
    cudaFuncSetAttribute(flash_h, cudaFuncAttributeMaxDynamicSharedMemorySize, FL_BYTES);
    cudaFuncSetAttribute(gemm_h,  cudaFuncAttributeMaxDynamicSharedMemorySize, G_BYTES);

    ln_kernel<<<M_TOT,256>>>(inputs,gamma,beta,xn);
    gemm_h<<<M_TOT/128,256,G_BYTES>>>(xn,      nullptr, Wq,bq, nullptr, nullptr, q16);
    gemm_h<<<M_TOT/128,256,G_BYTES>>>(context, nullptr, Wk,bk, nullptr, nullptr, k16);
    gemm_h<<<M_TOT/128,256,G_BYTES>>>(context, nullptr, Wv,bv, nullptr, nullptr, v16);
    flash_h<<<dim3(SS/64, BN), 256, FL_BYTES>>>(q16,k16,v16,o16);
    gemm_h<<<M_TOT/128,256,G_BYTES>>>(nullptr, o16,     Wp,bp, xn, out, nullptr);
}

// round 7
// speedup vs baseline: 8.4399x; 1.1471x over previous
#include <cuda_runtime.h>
#include <cuda_fp16.h>
#include <math.h>
#include <stdint.h>

#define BN 4
#define SS 4096
#define CC 256
#define M_TOT (BN*SS)

__device__ float  g_xn [(size_t)BN*SS*CC];
__device__ __half g_q16[(size_t)BN*SS*CC];
__device__ __half g_k16[(size_t)BN*SS*CC];
__device__ __half g_v16[(size_t)BN*SS*CC];
__device__ __half g_o16[(size_t)BN*SS*CC];

__device__ __forceinline__ uint32_t smem_u32(const void* p){
    uint32_t a; asm("{ .reg .u64 t; cvta.to.shared.u64 t, %1; cvt.u32.u64 %0, t; }":"=r"(a):"l"(p)); return a;
}
#define MMAH(d,a0,a1,a2,a3,b0,b1) \
    asm volatile("mma.sync.aligned.m16n8k16.row.col.f32.f16.f16.f32 {%0,%1,%2,%3},{%4,%5,%6,%7},{%8,%9},{%0,%1,%2,%3};" \
        :"+f"(d[0]),"+f"(d[1]),"+f"(d[2]),"+f"(d[3]) \
        :"r"(a0),"r"(a1),"r"(a2),"r"(a3),"r"(b0),"r"(b1))
#define LDSM4(r0,r1,r2,r3,a) asm volatile("ldmatrix.sync.aligned.m8n8.x4.shared.b16 {%0,%1,%2,%3},[%4];" \
        :"=r"(r0),"=r"(r1),"=r"(r2),"=r"(r3):"r"(a))
#define LDSM4T(r0,r1,r2,r3,a) asm volatile("ldmatrix.sync.aligned.m8n8.x4.trans.shared.b16 {%0,%1,%2,%3},[%4];" \
        :"=r"(r0),"=r"(r1),"=r"(r2),"=r"(r3):"r"(a))
#define CPAH(off_h, src) asm volatile("cp.async.cg.shared.global [%0], [%1], 16;"::"r"(smb+(uint32_t)((off_h)*2)),"l"(src):"memory")
#define CPC()  asm volatile("cp.async.commit_group;":::"memory")
#define CPW0() asm volatile("cp.async.wait_group 0;":::"memory")
#define CPW1() asm volatile("cp.async.wait_group 1;":::"memory")
__device__ __forceinline__ uint32_t h2u(__half2 x){ return *(uint32_t*)&x; }

// ---------------- LayerNorm: warp per row ----------------
__global__ void ln_kernel(const float* __restrict__ x, const float* __restrict__ gamma,
                          const float* __restrict__ beta, float* __restrict__ out){
    int wid = threadIdx.x>>5, lane = threadIdx.x&31;
    size_t row = (size_t)blockIdx.x*8 + wid;
    const float* xr = x + row*CC + lane*8;
    float4 v0 = *(const float4*)xr, v1 = *(const float4*)(xr+4);
    float s = v0.x+v0.y+v0.z+v0.w+v1.x+v1.y+v1.z+v1.w;
    #pragma unroll
    for(int o=16;o;o>>=1) s += __shfl_xor_sync(~0u,s,o);
    float mu = s*(1.f/CC);
    v0.x-=mu;v0.y-=mu;v0.z-=mu;v0.w-=mu;v1.x-=mu;v1.y-=mu;v1.z-=mu;v1.w-=mu;
    float q = v0.x*v0.x+v0.y*v0.y+v0.z*v0.z+v0.w*v0.w+v1.x*v1.x+v1.y*v1.y+v1.z*v1.z+v1.w*v1.w;
    #pragma unroll
    for(int o=16;o;o>>=1) q += __shfl_xor_sync(~0u,q,o);
    float rs = rsqrtf(q*(1.f/CC)+1e-3f);
    const float4 ga0 = *(const float4*)(gamma+lane*8), ga1 = *(const float4*)(gamma+lane*8+4);
    const float4 be0 = *(const float4*)(beta +lane*8), be1 = *(const float4*)(beta +lane*8+4);
    float4 o0,o1;
    o0.x=v0.x*rs*ga0.x+be0.x; o0.y=v0.y*rs*ga0.y+be0.y; o0.z=v0.z*rs*ga0.z+be0.z; o0.w=v0.w*rs*ga0.w+be0.w;
    o1.x=v1.x*rs*ga1.x+be1.x; o1.y=v1.y*rs*ga1.y+be1.y; o1.z=v1.z*rs*ga1.z+be1.z; o1.w=v1.w*rs*ga1.w+be1.w;
    float* op = out + row*CC + lane*8;
    *(float4*)op = o0; *(float4*)(op+4) = o1;
}

// ---------------- fp16 mma GEMM (1 or 2 weight passes) ----------------
// smem halfs: A[128][256] @0 (64KB); W[256][256] @32768 (128KB). 192KB total.
#define GW 32768
#define G_BYTES 196608
__global__ void __launch_bounds__(256,1) gemm_h(const float* __restrict__ A32,
        const __half* __restrict__ A16,
        const float* __restrict__ W1, const float* __restrict__ b1, __half* __restrict__ o16a,
        const float* __restrict__ W2, const float* __restrict__ b2, __half* __restrict__ o16b,
        const float* __restrict__ res, float* __restrict__ out32){
    extern __shared__ __half sh[];
    const uint32_t smb = smem_u32(sh);
    int tid=threadIdx.x, lane=tid&31, wid=tid>>5;
    int g=lane>>2, tig=lane&3, p=wid>>1, h=wid&1;
    int m0 = blockIdx.x*128;
    // stage A
    if(A32){
        #pragma unroll
        for(int i=0;i<16;i++){ int c=tid+i*256, r=c>>5, ch=c&31;
            const float4* s=(const float4*)(A32 + (size_t)(m0+r)*256 + ch*8);
            float4 u=s[0], w=s[1];
            uint4 pk = make_uint4(h2u(__floats2half2_rn(u.x,u.y)), h2u(__floats2half2_rn(u.z,u.w)),
                                  h2u(__floats2half2_rn(w.x,w.y)), h2u(__floats2half2_rn(w.z,w.w)));
            *(uint4*)(sh + r*256 + ((ch^(r&7))<<3)) = pk; }
    } else {
        #pragma unroll
        for(int i=0;i<16;i++){ int c=tid+i*256, r=c>>5, ch=c&31;
            uint4 u = *(const uint4*)(A16 + (size_t)(m0+r)*256 + ch*8);
            *(uint4*)(sh + r*256 + ((ch^(r&7))<<3)) = u; }
    }
    const int ria = (lane&7)+(lane&8);
    const int hi=(lane>>4)&1, sel=(lane>>3)&1, r7=lane&7;
    const int nsel = lane>>4;
    int npass = W2 ? 2 : 1;
    for(int pass=0; pass<npass; pass++){
        const float* W = pass ? W2 : W1;
        const float* bias = pass ? b2 : b1;
        __half* o16 = pass ? o16b : o16a;
        #pragma unroll
        for(int i=0;i<32;i++){ int c=tid+i*256, kr=c>>5, ch=c&31;
            const float4* s=(const float4*)(W + (size_t)kr*256 + ch*8);
            float4 u=s[0], w=s[1];
            uint4 pk = make_uint4(h2u(__floats2half2_rn(u.x,u.y)), h2u(__floats2half2_rn(u.z,u.w)),
                                  h2u(__floats2half2_rn(w.x,w.y)), h2u(__floats2half2_rn(w.z,w.w)));
            *(uint4*)(sh + GW + kr*256 + ((ch^(kr&7))<<3)) = pk; }
        __syncthreads();
        float acc[2][16][4];
        #pragma unroll
        for(int rt=0;rt<2;rt++) for(int n=0;n<16;n++){ acc[rt][n][0]=0.f;acc[rt][n][1]=0.f;acc[rt][n][2]=0.f;acc[rt][n][3]=0.f; }
        int row0 = p*32 + ria, row1 = row0 + 16;
        uint32_t a0b = smb + (uint32_t)row0*512, a1b = smb + (uint32_t)row1*512;
        int x0 = row0&7;
        #pragma unroll
        for(int ki=0;ki<16;ki++){
            uint32_t qa0,qa1,qa2,qa3, ra0,ra1,ra2,ra3;
            LDSM4(qa0,qa1,qa2,qa3, a0b + (uint32_t)(((2*ki+hi)^x0)<<4));
            LDSM4(ra0,ra1,ra2,ra3, a1b + (uint32_t)(((2*ki+hi)^x0)<<4));
            int krow = ki*16 + sel*8 + r7;
            uint32_t wr = smb + 65536u + (uint32_t)krow*512; int xw=krow&7;
            #pragma unroll
            for(int j=0;j<8;j++){
                int nt = h*16 + 2*j + nsel;
                uint32_t b0,b1,b2,b3;
                LDSM4T(b0,b1,b2,b3, wr + (uint32_t)((nt^xw)<<4));
                MMAH(acc[0][2*j],   qa0,qa1,qa2,qa3, b0,b1);
                MMAH(acc[0][2*j+1], qa0,qa1,qa2,qa3, b2,b3);
                MMAH(acc[1][2*j],   ra0,ra1,ra2,ra3, b0,b1);
                MMAH(acc[1][2*j+1], ra0,ra1,ra2,ra3, b2,b3);
            }
        }
        #pragma unroll
        for(int rt=0;rt<2;rt++){
            int rr = m0 + p*32 + rt*16 + g;
            #pragma unroll
            for(int n=0;n<16;n++){
                int col = h*128 + n*8 + 2*tig;
                float2 bb = *(const float2*)&bias[col];
                float v0=acc[rt][n][0]+bb.x, v1=acc[rt][n][1]+bb.y;
                float v2=acc[rt][n][2]+bb.x, v3=acc[rt][n][3]+bb.y;
                if(out32){
                    float2 y0=*(const float2*)&res[(size_t)rr*256+col];
                    float2 y1=*(const float2*)&res[(size_t)(rr+8)*256+col];
                    float2 w0={v0+y0.x,v1+y0.y}, w1={v2+y1.x,v3+y1.y};
                    *(float2*)&out32[(size_t)rr*256+col]=w0;
                    *(float2*)&out32[(size_t)(rr+8)*256+col]=w1;
                } else {
                    *(__half2*)(o16+(size_t)rr*256+col)     = __floats2half2_rn(v0,v1);
                    *(__half2*)(o16+(size_t)(rr+8)*256+col) = __floats2half2_rn(v2,v3);
                }
            }
        }
        if(pass+1<npass) __syncthreads();
    }
}

// ---------------- fp16 mma flash attention, Bq=128 ----------------
// smem halfs: Q@0 (32768); K@32768 (2x8192); V@49152 (2x8192); P@65536 (8x640). 141312 B
#define FK 32768
#define FV 49152
#define FP 65536
#define FL_BYTES 141312
__global__ void __launch_bounds__(256,1) flash_h(const __half* __restrict__ q,
        const __half* __restrict__ k, const __half* __restrict__ v, __half* __restrict__ o){
    extern __shared__ __half sh[];
    const uint32_t smb = smem_u32(sh);
    int tid=threadIdx.x, lane=tid&31, wid=tid>>5;
    int g=lane>>2, tig=lane&3;
    int b=blockIdx.y, qb=blockIdx.x;
    const __half* qg = q + ((size_t)b*SS + (size_t)qb*128)*CC;
    const __half* kg = k + (size_t)b*SS*CC;
    const __half* vg = v + (size_t)b*SS*CC;

    #pragma unroll
    for(int i=0;i<16;i++){ int c=tid+i*256, r=c>>5, ch=c&31;
        CPAH(r*256 + ((ch^(r&7))<<3), qg + (size_t)c*8); }
    #pragma unroll
    for(int i=0;i<4;i++){ int c=tid+i*256, r=c>>5, ch=c&31;
        int sw = r*256 + ((ch^(r&7))<<3);
        CPAH(FK + sw, kg + (size_t)c*8);
        CPAH(FV + sw, vg + (size_t)c*8); }
    CPC();

    float acc[32][4];
    #pragma unroll
    for(int i=0;i<32;i++){ acc[i][0]=0.f;acc[i][1]=0.f;acc[i][2]=0.f;acc[i][3]=0.f; }
    float l0=0.f, l1=0.f;
    const int ria=(lane&7)+(lane&8), hi=(lane>>4)&1, sel=(lane>>3)&1, r7=lane&7, nsel=lane>>4;
    const int rq = wid*16 + ria; const int rq7 = rq&7;
    const uint32_t aqb = smb + (uint32_t)rq*512;
    const int kkey = (lane&7) + ((lane>>4)<<3);       // QK b-frag key-in-group
    const int kcs  = (lane>>3)&1;                      // QK b-frag k-half
    const uint32_t apb = smb + (uint32_t)(FP + wid*640)*2 + (uint32_t)ria*80;
    __half2* psm = (__half2*)(sh + FP + wid*640);

    for(int t=0;t<128;t++){
        int buf=t&1;
        if(t<127){
            const __half* kt = kg + (size_t)(t+1)*8192;
            const __half* vt = vg + (size_t)(t+1)*8192;
            int bo = (buf^1)*8192;
            #pragma unroll
            for(int i=0;i<4;i++){ int c=tid+i*256, r=c>>5, ch=c&31;
                int sw = r*256 + ((ch^(r&7))<<3);
                CPAH(FK + bo + sw, kt + (size_t)c*8);
                CPAH(FV + bo + sw, vt + (size_t)c*8); }
            CPC(); CPW1();
        } else CPW0();
        __syncthreads();
        uint32_t kbb = smb + (uint32_t)(FK + buf*8192)*2;
        uint32_t vbb = smb + (uint32_t)(FV + buf*8192)*2;
        float s[4][4];
        #pragma unroll
        for(int n=0;n<4;n++){ s[n][0]=0.f;s[n][1]=0.f;s[n][2]=0.f;s[n][3]=0.f; }
        #pragma unroll
        for(int ki=0;ki<16;ki++){
            uint32_t a0,a1,a2,a3, b0,b1,b2,b3, c0,c1,c2,c3;
            LDSM4(a0,a1,a2,a3, aqb + (uint32_t)(((2*ki+hi)^rq7)<<4));
            LDSM4(b0,b1,b2,b3, kbb + (uint32_t)kkey*512      + (uint32_t)(((2*ki+kcs)^(kkey&7))<<4));
            LDSM4(c0,c1,c2,c3, kbb + (uint32_t)(16+kkey)*512 + (uint32_t)(((2*ki+kcs)^(kkey&7))<<4));
            MMAH(s[0], a0,a1,a2,a3, b0,b1);
            MMAH(s[1], a0,a1,a2,a3, b2,b3);
            MMAH(s[2], a0,a1,a2,a3, c0,c1);
            MMAH(s[3], a0,a1,a2,a3, c2,c3);
        }
        const float SC=0.0625f;
        #pragma unroll
        for(int n=0;n<4;n++){
            float e0=__expf(s[n][0]*SC), e1=__expf(s[n][1]*SC);
            float e2=__expf(s[n][2]*SC), e3=__expf(s[n][3]*SC);
            l0 += e0+e1; l1 += e2+e3;
            psm[g*20 + n*4 + tig]       = __floats2half2_rn(e0,e1);
            psm[(g+8)*20 + n*4 + tig]   = __floats2half2_rn(e2,e3);
        }
        __syncwarp();
        #pragma unroll
        for(int kp=0;kp<2;kp++){
            uint32_t pa0,pa1,pa2,pa3;
            LDSM4(pa0,pa1,pa2,pa3, apb + (uint32_t)((kp*2+hi)<<4));
            int krow = kp*16 + sel*8 + r7;
            uint32_t vr = vbb + (uint32_t)krow*512; int xv=krow&7;
            #pragma unroll
            for(int j=0;j<16;j++){
                int nt = 2*j + nsel;
                uint32_t b0,b1,b2,b3;
                LDSM4T(b0,b1,b2,b3, vr + (uint32_t)((nt^xv)<<4));
                MMAH(acc[2*j],   pa0,pa1,pa2,pa3, b0,b1);
                MMAH(acc[2*j+1], pa0,pa1,pa2,pa3, b2,b3);
            }
        }
        __syncthreads();
    }
    l0 += __shfl_xor_sync(~0u,l0,1); l0 += __shfl_xor_sync(~0u,l0,2);
    l1 += __shfl_xor_sync(~0u,l1,1); l1 += __shfl_xor_sync(~0u,l1,2);
    float inv0 = 1.f/l0, inv1 = 1.f/l1;
    __half* o0 = o + ((size_t)b*SS + (size_t)qb*128 + wid*16 + g)*CC;
    __half* o1 = o0 + 8*CC;
    #pragma unroll
    for(int n=0;n<32;n++){
        int col = n*8 + 2*tig;
        *(__half2*)(o0+col) = __floats2half2_rn(acc[n][0]*inv0, acc[n][1]*inv0);
        *(__half2*)(o1+col) = __floats2half2_rn(acc[n][2]*inv1, acc[n][3]*inv1);
    }
}

// ---------------- launcher ----------------
extern "C" void kernel_launch(void* const* d_in, const int* in_sizes, int n_in,
                              void* d_out, int out_size){
    const float* inputs  = (const float*)d_in[0];
    const float* context = (const float*)d_in[1];
    const float* Wq=(const float*)d_in[2];  const float* bq=(const float*)d_in[3];
    const float* Wk=(const float*)d_in[4];  const float* bk=(const float*)d_in[5];
    const float* Wv=(const float*)d_in[6];  const float* bv=(const float*)d_in[7];
    const float* Wp=(const float*)d_in[8];  const float* bp=(const float*)d_in[9];
    const float* gamma=(const float*)d_in[10]; const float* beta=(const float*)d_in[11];
    float* out=(float*)d_out;
    float *xn; __half *q16,*k16,*v16,*o16;
    cudaGetSymbolAddress((void**)&xn,g_xn);
    cudaGetSymbolAddress((void**)&q16,g_q16); cudaGetSymbolAddress((void**)&k16,g_k16);
    cudaGetSymbolAddress((void**)&v16,g_v16); cudaGetSymbolAddress((void**)&o16,g_o16);
    cudaFuncSetAttribute(flash_h, cudaFuncAttributeMaxDynamicSharedMemorySize, FL_BYTES);
    cudaFuncSetAttribute(gemm_h,  cudaFuncAttributeMaxDynamicSharedMemorySize, G_BYTES);

    ln_kernel<<<M_TOT/8,256>>>(inputs,gamma,beta,xn);
    gemm_h<<<M_TOT/128,256,G_BYTES>>>(xn, nullptr, Wq,bq,q16, nullptr,nullptr,nullptr, nullptr,nullptr);
    gemm_h<<<M_TOT/128,256,G_BYTES>>>(context, nullptr, Wk,bk,k16, Wv,bv,v16, nullptr,nullptr);
    flash_h<<<dim3(SS/128, BN), 256, FL_BYTES>>>(q16,k16,v16,o16);
    gemm_h<<<M_TOT/128,256,G_BYTES>>>(nullptr, o16, Wp,bp,nullptr, nullptr,nullptr,nullptr, xn, out);
}

// round 8
// speedup vs baseline: 9.3353x; 1.1061x over previous
#include <cuda_runtime.h>
#include <cuda_fp16.h>
#include <math.h>
#include <stdint.h>

#define BN 4
#define SS 4096
#define CC 256
#define M_TOT (BN*SS)

__device__ float  g_xn  [(size_t)BN*SS*CC];
__device__ __half g_xn16[(size_t)BN*SS*CC];
__device__ __half g_ct16[(size_t)BN*SS*CC];
__device__ __half g_q16 [(size_t)BN*SS*CC];
__device__ __half g_k16 [(size_t)BN*SS*CC];
__device__ __half g_v16 [(size_t)BN*SS*CC];
__device__ __half g_o16 [(size_t)BN*SS*CC];
__device__ __half g_wq16[CC*CC];
__device__ __half g_wk16[CC*CC];
__device__ __half g_wv16[CC*CC];
__device__ __half g_wp16[CC*CC];

__device__ __forceinline__ uint32_t smem_u32(const void* p){
    uint32_t a; asm("{ .reg .u64 t; cvta.to.shared.u64 t, %1; cvt.u32.u64 %0, t; }":"=r"(a):"l"(p)); return a;
}
#define MMAH(d,a0,a1,a2,a3,b0,b1) \
    asm volatile("mma.sync.aligned.m16n8k16.row.col.f32.f16.f16.f32 {%0,%1,%2,%3},{%4,%5,%6,%7},{%8,%9},{%0,%1,%2,%3};" \
        :"+f"(d[0]),"+f"(d[1]),"+f"(d[2]),"+f"(d[3]) \
        :"r"(a0),"r"(a1),"r"(a2),"r"(a3),"r"(b0),"r"(b1))
#define LDSM4(r0,r1,r2,r3,a) asm volatile("ldmatrix.sync.aligned.m8n8.x4.shared.b16 {%0,%1,%2,%3},[%4];" \
        :"=r"(r0),"=r"(r1),"=r"(r2),"=r"(r3):"r"(a))
#define LDSM4T(r0,r1,r2,r3,a) asm volatile("ldmatrix.sync.aligned.m8n8.x4.trans.shared.b16 {%0,%1,%2,%3},[%4];" \
        :"=r"(r0),"=r"(r1),"=r"(r2),"=r"(r3):"r"(a))
#define CPAH(off_h, src) asm volatile("cp.async.cg.shared.global [%0], [%1], 16;"::"r"(smb+(uint32_t)((off_h)*2)),"l"(src):"memory")
#define CPC()  asm volatile("cp.async.commit_group;":::"memory")
#define CPW0() asm volatile("cp.async.wait_group 0;":::"memory")
#define CPW1() asm volatile("cp.async.wait_group 1;":::"memory")
__device__ __forceinline__ uint32_t h2u(__half2 x){ return *(uint32_t*)&x; }

// ---------------- LayerNorm: warp/row, dual fp32+fp16 out ----------------
__global__ void ln_kernel(const float* __restrict__ x, const float* __restrict__ gamma,
                          const float* __restrict__ beta, float* __restrict__ out32,
                          __half* __restrict__ out16){
    int wid = threadIdx.x>>5, lane = threadIdx.x&31;
    size_t row = (size_t)blockIdx.x*8 + wid;
    const float* xr = x + row*CC + lane*8;
    float4 v0 = *(const float4*)xr, v1 = *(const float4*)(xr+4);
    float s = v0.x+v0.y+v0.z+v0.w+v1.x+v1.y+v1.z+v1.w;
    #pragma unroll
    for(int o=16;o;o>>=1) s += __shfl_xor_sync(~0u,s,o);
    float mu = s*(1.f/CC);
    v0.x-=mu;v0.y-=mu;v0.z-=mu;v0.w-=mu;v1.x-=mu;v1.y-=mu;v1.z-=mu;v1.w-=mu;
    float q = v0.x*v0.x+v0.y*v0.y+v0.z*v0.z+v0.w*v0.w+v1.x*v1.x+v1.y*v1.y+v1.z*v1.z+v1.w*v1.w;
    #pragma unroll
    for(int o=16;o;o>>=1) q += __shfl_xor_sync(~0u,q,o);
    float rs = rsqrtf(q*(1.f/CC)+1e-3f);
    const float4 ga0 = *(const float4*)(gamma+lane*8), ga1 = *(const float4*)(gamma+lane*8+4);
    const float4 be0 = *(const float4*)(beta +lane*8), be1 = *(const float4*)(beta +lane*8+4);
    float4 o0,o1;
    o0.x=v0.x*rs*ga0.x+be0.x; o0.y=v0.y*rs*ga0.y+be0.y; o0.z=v0.z*rs*ga0.z+be0.z; o0.w=v0.w*rs*ga0.w+be0.w;
    o1.x=v1.x*rs*ga1.x+be1.x; o1.y=v1.y*rs*ga1.y+be1.y; o1.z=v1.z*rs*ga1.z+be1.z; o1.w=v1.w*rs*ga1.w+be1.w;
    float* op = out32 + row*CC + lane*8;
    *(float4*)op = o0; *(float4*)(op+4) = o1;
    uint4 hp = make_uint4(h2u(__floats2half2_rn(o0.x,o0.y)), h2u(__floats2half2_rn(o0.z,o0.w)),
                          h2u(__floats2half2_rn(o1.x,o1.y)), h2u(__floats2half2_rn(o1.z,o1.w)));
    *(uint4*)(out16 + row*CC + lane*8) = hp;
}

// ---------------- fp32 -> fp16 bulk convert ----------------
__global__ void cvt_half(const float* __restrict__ src, __half* __restrict__ dst){
    size_t i = ((size_t)blockIdx.x*256 + threadIdx.x)*8;
    float4 a=*(const float4*)(src+i), b=*(const float4*)(src+i+4);
    uint4 r = make_uint4(h2u(__floats2half2_rn(a.x,a.y)),h2u(__floats2half2_rn(a.z,a.w)),
                         h2u(__floats2half2_rn(b.x,b.y)),h2u(__floats2half2_rn(b.z,b.w)));
    *(uint4*)(dst+i)=r;
}

// ---------------- fp16 mma GEMM, up to 3 passes, cp.async staging ----------------
// smem halfs: A[128][256] @0 (64KB); W[256][256] @32768 (128KB).
#define GW 32768
#define G_BYTES 196608
__global__ void __launch_bounds__(256,1) gemm_h(
        const __half* __restrict__ A1, const __half* __restrict__ W1, const float* __restrict__ b1, __half* __restrict__ o1,
        const __half* __restrict__ A2, const __half* __restrict__ W2, const float* __restrict__ b2, __half* __restrict__ o2,
        const __half* __restrict__ W3, const float* __restrict__ b3, __half* __restrict__ o3,
        const float* __restrict__ res, float* __restrict__ out32){
    extern __shared__ __half sh[];
    const uint32_t smb = smem_u32(sh);
    int tid=threadIdx.x, lane=tid&31, wid=tid>>5;
    int g=lane>>2, tig=lane&3, p=wid>>1, h=wid&1;
    int m0 = blockIdx.x*128;
    const int ria=(lane&7)+(lane&8), hi=(lane>>4)&1, sel=(lane>>3)&1, r7=lane&7, nsel=lane>>4;

    auto stageA = [&](const __half* A){
        #pragma unroll
        for(int i=0;i<16;i++){ int c=tid+i*256, r=c>>5, ch=c&31;
            CPAH(r*256 + ((ch^(r&7))<<3), A + (size_t)(m0+r)*256 + ch*8); }
    };
    auto stageW = [&](const __half* W){
        #pragma unroll
        for(int i=0;i<32;i++){ int c=tid+i*256, kr=c>>5, ch=c&31;
            CPAH(GW + kr*256 + ((ch^(kr&7))<<3), W + (size_t)kr*256 + ch*8); }
    };
    auto compute = [&](const float* bias, __half* o16){
        float acc[2][16][4];
        #pragma unroll
        for(int rt=0;rt<2;rt++) for(int n=0;n<16;n++){ acc[rt][n][0]=0.f;acc[rt][n][1]=0.f;acc[rt][n][2]=0.f;acc[rt][n][3]=0.f; }
        int row0 = p*32 + ria, row1 = row0 + 16;
        uint32_t a0b = smb + (uint32_t)row0*512, a1b = smb + (uint32_t)row1*512;
        int x0 = row0&7;
        #pragma unroll
        for(int ki=0;ki<16;ki++){
            uint32_t qa0,qa1,qa2,qa3, ra0,ra1,ra2,ra3;
            LDSM4(qa0,qa1,qa2,qa3, a0b + (uint32_t)(((2*ki+hi)^x0)<<4));
            LDSM4(ra0,ra1,ra2,ra3, a1b + (uint32_t)(((2*ki+hi)^x0)<<4));
            int krow = ki*16 + sel*8 + r7;
            uint32_t wr = smb + 65536u + (uint32_t)krow*512; int xw=krow&7;
            #pragma unroll
            for(int j=0;j<8;j++){
                int nt = h*16 + 2*j + nsel;
                uint32_t b0,b1,b2,b3;
                LDSM4T(b0,b1,b2,b3, wr + (uint32_t)((nt^xw)<<4));
                MMAH(acc[0][2*j],   qa0,qa1,qa2,qa3, b0,b1);
                MMAH(acc[0][2*j+1], qa0,qa1,qa2,qa3, b2,b3);
                MMAH(acc[1][2*j],   ra0,ra1,ra2,ra3, b0,b1);
                MMAH(acc[1][2*j+1], ra0,ra1,ra2,ra3, b2,b3);
            }
        }
        #pragma unroll
        for(int rt=0;rt<2;rt++){
            int rr = m0 + p*32 + rt*16 + g;
            #pragma unroll
            for(int n=0;n<16;n++){
                int col = h*128 + n*8 + 2*tig;
                float2 bb = *(const float2*)&bias[col];
                float v0=acc[rt][n][0]+bb.x, v1=acc[rt][n][1]+bb.y;
                float v2=acc[rt][n][2]+bb.x, v3=acc[rt][n][3]+bb.y;
                if(out32){
                    float2 y0=*(const float2*)&res[(size_t)rr*256+col];
                    float2 y1=*(const float2*)&res[(size_t)(rr+8)*256+col];
                    float2 w0={v0+y0.x,v1+y0.y}, w1={v2+y1.x,v3+y1.y};
                    *(float2*)&out32[(size_t)rr*256+col]=w0;
                    *(float2*)&out32[(size_t)(rr+8)*256+col]=w1;
                } else {
                    *(__half2*)(o16+(size_t)rr*256+col)     = __floats2half2_rn(v0,v1);
                    *(__half2*)(o16+(size_t)(rr+8)*256+col) = __floats2half2_rn(v2,v3);
                }
            }
        }
    };

    stageA(A1); stageW(W1); CPC(); CPW0(); __syncthreads();
    compute(b1, o1);
    if(W2){
        __syncthreads();
        stageA(A2); stageW(W2); CPC(); CPW0(); __syncthreads();
        compute(b2, o2);
        if(W3){
            __syncthreads();
            stageW(W3); CPC(); CPW0(); __syncthreads();
            compute(b3, o3);
        }
    }
}

// ---------------- fp16 mma flash attention, Bq=128, P-in-registers ----------------
// smem halfs: Q@0 (32768); K@32768 (3x8192); V@57344 (3x8192). 163840 B.
#define FK 32768
#define FV 57344
#define FL_BYTES 163840
__global__ void __launch_bounds__(256,1) flash_h(const __half* __restrict__ q,
        const __half* __restrict__ k, const __half* __restrict__ v, __half* __restrict__ o){
    extern __shared__ __half sh[];
    const uint32_t smb = smem_u32(sh);
    int tid=threadIdx.x, lane=tid&31, wid=tid>>5;
    int g=lane>>2, tig=tid&3;
    int b=blockIdx.y, qb=blockIdx.x;
    const __half* qg = q + ((size_t)b*SS + (size_t)qb*128)*CC;
    const __half* kg = k + (size_t)b*SS*CC;
    const __half* vg = v + (size_t)b*SS*CC;

    // group 0: Q + K0 + V0 into slot 0
    #pragma unroll
    for(int i=0;i<16;i++){ int c=tid+i*256, r=c>>5, ch=c&31;
        CPAH(r*256 + ((ch^(r&7))<<3), qg + (size_t)c*8); }
    #pragma unroll
    for(int i=0;i<4;i++){ int c=tid+i*256, r=c>>5, ch=c&31;
        int sw = r*256 + ((ch^(r&7))<<3);
        CPAH(FK + sw, kg + (size_t)c*8);
        CPAH(FV + sw, vg + (size_t)c*8); }
    CPC();

    float acc[32][4];
    #pragma unroll
    for(int i=0;i<32;i++){ acc[i][0]=0.f;acc[i][1]=0.f;acc[i][2]=0.f;acc[i][3]=0.f; }
    float l0=0.f, l1=0.f;
    const int hi=(lane>>4)&1, sel=(lane>>3)&1, r7=lane&7, nsel=lane>>4;
    const int rq = wid*16 + (lane&7) + (lane&8); const int rq7 = rq&7;
    const uint32_t aqb = smb + (uint32_t)rq*512;
    const int kkey = (lane&7) + ((lane>>4)<<3);
    const int kcs  = (lane>>3)&1;

    int buf=0, nxt=1;
    for(int t=0;t<128;t++){
        if(t<127){
            const __half* kt = kg + (size_t)(t+1)*8192;
            const __half* vt = vg + (size_t)(t+1)*8192;
            int bo = nxt*8192;
            #pragma unroll
            for(int i=0;i<4;i++){ int c=tid+i*256, r=c>>5, ch=c&31;
                int sw = r*256 + ((ch^(r&7))<<3);
                CPAH(FK + bo + sw, kt + (size_t)c*8);
                CPAH(FV + bo + sw, vt + (size_t)c*8); }
            CPC(); CPW1();
        } else CPW0();
        __syncthreads();
        uint32_t kbb = smb + (uint32_t)(FK + buf*8192)*2;
        uint32_t vbb = smb + (uint32_t)(FV + buf*8192)*2;
        float s[4][4];
        #pragma unroll
        for(int n=0;n<4;n++){ s[n][0]=0.f;s[n][1]=0.f;s[n][2]=0.f;s[n][3]=0.f; }
        #pragma unroll
        for(int ki=0;ki<16;ki++){
            uint32_t a0,a1,a2,a3, b0,b1,b2,b3, c0,c1,c2,c3;
            LDSM4(a0,a1,a2,a3, aqb + (uint32_t)(((2*ki+hi)^rq7)<<4));
            LDSM4(b0,b1,b2,b3, kbb + (uint32_t)kkey*512      + (uint32_t)(((2*ki+kcs)^(kkey&7))<<4));
            LDSM4(c0,c1,c2,c3, kbb + (uint32_t)(16+kkey)*512 + (uint32_t)(((2*ki+kcs)^(kkey&7))<<4));
            MMAH(s[0], a0,a1,a2,a3, b0,b1);
            MMAH(s[1], a0,a1,a2,a3, b2,b3);
            MMAH(s[2], a0,a1,a2,a3, c0,c1);
            MMAH(s[3], a0,a1,a2,a3, c2,c3);
        }
        // softmax in registers: D-frag -> exp (f16x2) -> PV A-frags directly
        const float C2 = 0.09016994f;   // log2(e)/16
        uint32_t pa[2][4];
        #pragma unroll
        for(int n=0;n<4;n++){
            uint32_t e0,e1;
            __half2 h0 = __floats2half2_rn(s[n][0]*C2, s[n][1]*C2);
            __half2 h1 = __floats2half2_rn(s[n][2]*C2, s[n][3]*C2);
            asm("ex2.approx.f16x2 %0, %1;":"=r"(e0):"r"(h2u(h0)));
            asm("ex2.approx.f16x2 %0, %1;":"=r"(e1):"r"(h2u(h1)));
            pa[n>>1][(n&1)*2]   = e0;
            pa[n>>1][(n&1)*2+1] = e1;
            float2 f0=__half22float2(*(__half2*)&e0), f1=__half22float2(*(__half2*)&e1);
            l0 += f0.x+f0.y; l1 += f1.x+f1.y;
        }
        #pragma unroll
        for(int kp=0;kp<2;kp++){
            int krow = kp*16 + sel*8 + r7;
            uint32_t vr = vbb + (uint32_t)krow*512; int xv=krow&7;
            #pragma unroll
            for(int j=0;j<16;j++){
                int nt = 2*j + nsel;
                uint32_t b0,b1,b2,b3;
                LDSM4T(b0,b1,b2,b3, vr + (uint32_t)((nt^xv)<<4));
                MMAH(acc[2*j],   pa[kp][0],pa[kp][1],pa[kp][2],pa[kp][3], b0,b1);
                MMAH(acc[2*j+1], pa[kp][0],pa[kp][1],pa[kp][2],pa[kp][3], b2,b3);
            }
        }
        buf = nxt; nxt = (nxt==2) ? 0 : nxt+1;
    }
    l0 += __shfl_xor_sync(~0u,l0,1); l0 += __shfl_xor_sync(~0u,l0,2);
    l1 += __shfl_xor_sync(~0u,l1,1); l1 += __shfl_xor_sync(~0u,l1,2);
    float inv0 = 1.f/l0, inv1 = 1.f/l1;
    __half* o0 = o + ((size_t)b*SS + (size_t)qb*128 + wid*16 + g)*CC;
    __half* o1 = o0 + 8*CC;
    #pragma unroll
    for(int n=0;n<32;n++){
        int col = n*8 + 2*tig;
        *(__half2*)(o0+col) = __floats2half2_rn(acc[n][0]*inv0, acc[n][1]*inv0);
        *(__half2*)(o1+col) = __floats2half2_rn(acc[n][2]*inv1, acc[n][3]*inv1);
    }
}

// ---------------- launcher ----------------
extern "C" void kernel_launch(void* const* d_in, const int* in_sizes, int n_in,
                              void* d_out, int out_size){
    const float* inputs  = (const float*)d_in[0];
    const float* context = (const float*)d_in[1];
    const float* Wq=(const float*)d_in[2];  const float* bq=(const float*)d_in[3];
    const float* Wk=(const float*)d_in[4];  const float* bk=(const float*)d_in[5];
    const float* Wv=(const float*)d_in[6];  const float* bv=(const float*)d_in[7];
    const float* Wp=(const float*)d_in[8];  const float* bp=(const float*)d_in[9];
    const float* gamma=(const float*)d_in[10]; const float* beta=(const float*)d_in[11];
    float* out=(float*)d_out;
    float *xn; __half *xn16,*ct16,*q16,*k16,*v16,*o16,*wq16,*wk16,*wv16,*wp16;
    cudaGetSymbolAddress((void**)&xn,g_xn);
    cudaGetSymbolAddress((void**)&xn16,g_xn16); cudaGetSymbolAddress((void**)&ct16,g_ct16);
    cudaGetSymbolAddress((void**)&q16,g_q16);   cudaGetSymbolAddress((void**)&k16,g_k16);
    cudaGetSymbolAddress((void**)&v16,g_v16);   cudaGetSymbolAddress((void**)&o16,g_o16);
    cudaGetSymbolAddress((void**)&wq16,g_wq16); cudaGetSymbolAddress((void**)&wk16,g_wk16);
    cudaGetSymbolAddress((void**)&wv16,g_wv16); cudaGetSymbolAddress((void**)&wp16,g_wp16);
    cudaFuncSetAttribute(flash_h, cudaFuncAttributeMaxDynamicSharedMemorySize, FL_BYTES);
    cudaFuncSetAttribute(gemm_h,  cudaFuncAttributeMaxDynamicSharedMemorySize, G_BYTES);

    ln_kernel<<<M_TOT/8,256>>>(inputs,gamma,beta,xn,xn16);
    cvt_half<<<M_TOT*CC/2048,256>>>(context, ct16);
    cvt_half<<<32,256>>>(Wq, wq16);
    cvt_half<<<32,256>>>(Wk, wk16);
    cvt_half<<<32,256>>>(Wv, wv16);
    cvt_half<<<32,256>>>(Wp, wp16);
    gemm_h<<<M_TOT/128,256,G_BYTES>>>(xn16, wq16,bq,q16,
                                      ct16, wk16,bk,k16,
                                      wv16,bv,v16, nullptr,nullptr);
    flash_h<<<dim3(SS/128, BN), 256, FL_BYTES>>>(q16,k16,v16,o16);
    gemm_h<<<M_TOT/128,256,G_BYTES>>>(o16, wp16,bp,nullptr,
                                      nullptr, nullptr,nullptr,nullptr,
                                      nullptr,nullptr,nullptr, xn, out);
}

// round 9
// speedup vs baseline: 10.1728x; 1.0897x over previous
#include <cuda_runtime.h>
#include <cuda_fp16.h>
#include <math.h>
#include <stdint.h>

#define BN 4
#define SS 4096
#define CC 256
#define M_TOT (BN*SS)

__device__ float  g_xn  [(size_t)BN*SS*CC];
__device__ __half g_xn16[(size_t)BN*SS*CC];
__device__ __half g_ct16[(size_t)BN*SS*CC];
__device__ __half g_q16 [(size_t)BN*SS*CC];
__device__ __half g_k16 [(size_t)BN*SS*CC];
__device__ __half g_v16 [(size_t)BN*SS*CC];
__device__ __half g_o16 [(size_t)BN*SS*CC];
__device__ __half g_wq16[CC*CC];
__device__ __half g_wk16[CC*CC];
__device__ __half g_wv16[CC*CC];
__device__ __half g_wp16[CC*CC];

__device__ __forceinline__ uint32_t smem_u32(const void* p){
    uint32_t a; asm("{ .reg .u64 t; cvta.to.shared.u64 t, %1; cvt.u32.u64 %0, t; }":"=r"(a):"l"(p)); return a;
}
#define MMAH(d,a0,a1,a2,a3,b0,b1) \
    asm volatile("mma.sync.aligned.m16n8k16.row.col.f32.f16.f16.f32 {%0,%1,%2,%3},{%4,%5,%6,%7},{%8,%9},{%0,%1,%2,%3};" \
        :"+f"(d[0]),"+f"(d[1]),"+f"(d[2]),"+f"(d[3]) \
        :"r"(a0),"r"(a1),"r"(a2),"r"(a3),"r"(b0),"r"(b1))
#define LDSM4(r0,r1,r2,r3,a) asm volatile("ldmatrix.sync.aligned.m8n8.x4.shared.b16 {%0,%1,%2,%3},[%4];" \
        :"=r"(r0),"=r"(r1),"=r"(r2),"=r"(r3):"r"(a))
#define LDSM4T(r0,r1,r2,r3,a) asm volatile("ldmatrix.sync.aligned.m8n8.x4.trans.shared.b16 {%0,%1,%2,%3},[%4];" \
        :"=r"(r0),"=r"(r1),"=r"(r2),"=r"(r3):"r"(a))
#define CPAH(off_h, src) asm volatile("cp.async.cg.shared.global [%0], [%1], 16;"::"r"(smb+(uint32_t)((off_h)*2)),"l"(src):"memory")
#define CPC()  asm volatile("cp.async.commit_group;":::"memory")
#define CPW0() asm volatile("cp.async.wait_group 0;":::"memory")
__device__ __forceinline__ uint32_t h2u(__half2 x){ return *(uint32_t*)&x; }

// ---------------- LayerNorm: warp/row, dual fp32+fp16 out ----------------
__global__ void ln_kernel(const float* __restrict__ x, const float* __restrict__ gamma,
                          const float* __restrict__ beta, float* __restrict__ out32,
                          __half* __restrict__ out16){
    int wid = threadIdx.x>>5, lane = threadIdx.x&31;
    size_t row = (size_t)blockIdx.x*8 + wid;
    const float* xr = x + row*CC + lane*8;
    float4 v0 = *(const float4*)xr, v1 = *(const float4*)(xr+4);
    float s = v0.x+v0.y+v0.z+v0.w+v1.x+v1.y+v1.z+v1.w;
    #pragma unroll
    for(int o=16;o;o>>=1) s += __shfl_xor_sync(~0u,s,o);
    float mu = s*(1.f/CC);
    v0.x-=mu;v0.y-=mu;v0.z-=mu;v0.w-=mu;v1.x-=mu;v1.y-=mu;v1.z-=mu;v1.w-=mu;
    float q = v0.x*v0.x+v0.y*v0.y+v0.z*v0.z+v0.w*v0.w+v1.x*v1.x+v1.y*v1.y+v1.z*v1.z+v1.w*v1.w;
    #pragma unroll
    for(int o=16;o;o>>=1) q += __shfl_xor_sync(~0u,q,o);
    float rs = rsqrtf(q*(1.f/CC)+1e-3f);
    const float4 ga0 = *(const float4*)(gamma+lane*8), ga1 = *(const float4*)(gamma+lane*8+4);
    const float4 be0 = *(const float4*)(beta +lane*8), be1 = *(const float4*)(beta +lane*8+4);
    float4 o0,o1;
    o0.x=v0.x*rs*ga0.x+be0.x; o0.y=v0.y*rs*ga0.y+be0.y; o0.z=v0.z*rs*ga0.z+be0.z; o0.w=v0.w*rs*ga0.w+be0.w;
    o1.x=v1.x*rs*ga1.x+be1.x; o1.y=v1.y*rs*ga1.y+be1.y; o1.z=v1.z*rs*ga1.z+be1.z; o1.w=v1.w*rs*ga1.w+be1.w;
    float* op = out32 + row*CC + lane*8;
    *(float4*)op = o0; *(float4*)(op+4) = o1;
    uint4 hp = make_uint4(h2u(__floats2half2_rn(o0.x,o0.y)), h2u(__floats2half2_rn(o0.z,o0.w)),
                          h2u(__floats2half2_rn(o1.x,o1.y)), h2u(__floats2half2_rn(o1.z,o1.w)));
    *(uint4*)(out16 + row*CC + lane*8) = hp;
}

// ---------------- fused fp32->fp16 convert: context + 4 weights ----------------
__global__ void cvt_all(const float* __restrict__ ctx, __half* __restrict__ dctx,
        const float* __restrict__ Wq, const float* __restrict__ Wk,
        const float* __restrict__ Wv, const float* __restrict__ Wp,
        __half* __restrict__ dwq, __half* __restrict__ dwk,
        __half* __restrict__ dwv, __half* __restrict__ dwp){
    int blk = blockIdx.x;
    const float* src; __half* dst; size_t base;
    if(blk < 2048){ src=ctx; dst=dctx; base=(size_t)blk*2048; }
    else{
        int w=(blk-2048)>>5, off=(blk-2048)&31;
        src = w==0?Wq : w==1?Wk : w==2?Wv : Wp;
        dst = w==0?dwq: w==1?dwk: w==2?dwv: dwp;
        base = (size_t)off*2048;
    }
    size_t i = base + (size_t)threadIdx.x*8;
    float4 a=*(const float4*)(src+i), b=*(const float4*)(src+i+4);
    uint4 r = make_uint4(h2u(__floats2half2_rn(a.x,a.y)),h2u(__floats2half2_rn(a.z,a.w)),
                         h2u(__floats2half2_rn(b.x,b.y)),h2u(__floats2half2_rn(b.z,b.w)));
    *(uint4*)(dst+i)=r;
}

// ---------------- fp16 mma GEMM, up to 3 passes, cp.async staging ----------------
#define GW 32768
#define G_BYTES 196608
__global__ void __launch_bounds__(256,1) gemm_h(
        const __half* __restrict__ A1, const __half* __restrict__ W1, const float* __restrict__ b1, __half* __restrict__ o1,
        const __half* __restrict__ A2, const __half* __restrict__ W2, const float* __restrict__ b2, __half* __restrict__ o2,
        const __half* __restrict__ W3, const float* __restrict__ b3, __half* __restrict__ o3,
        const float* __restrict__ res, float* __restrict__ out32){
    extern __shared__ __half sh[];
    const uint32_t smb = smem_u32(sh);
    int tid=threadIdx.x, lane=tid&31, wid=tid>>5;
    int g=lane>>2, tig=lane&3, p=wid>>1, h=wid&1;
    int m0 = blockIdx.x*128;
    const int ria=(lane&7)+(lane&8), hi=(lane>>4)&1, sel=(lane>>3)&1, r7=lane&7, nsel=lane>>4;

    auto stageA = [&](const __half* A){
        #pragma unroll
        for(int i=0;i<16;i++){ int c=tid+i*256, r=c>>5, ch=c&31;
            CPAH(r*256 + ((ch^(r&7))<<3), A + (size_t)(m0+r)*256 + ch*8); }
    };
    auto stageW = [&](const __half* W){
        #pragma unroll
        for(int i=0;i<32;i++){ int c=tid+i*256, kr=c>>5, ch=c&31;
            CPAH(GW + kr*256 + ((ch^(kr&7))<<3), W + (size_t)kr*256 + ch*8); }
    };
    auto compute = [&](const float* bias, __half* o16){
        float acc[2][16][4];
        #pragma unroll
        for(int rt=0;rt<2;rt++) for(int n=0;n<16;n++){ acc[rt][n][0]=0.f;acc[rt][n][1]=0.f;acc[rt][n][2]=0.f;acc[rt][n][3]=0.f; }
        int row0 = p*32 + ria, row1 = row0 + 16;
        uint32_t a0b = smb + (uint32_t)row0*512, a1b = smb + (uint32_t)row1*512;
        int x0 = row0&7;
        #pragma unroll
        for(int ki=0;ki<16;ki++){
            uint32_t qa0,qa1,qa2,qa3, ra0,ra1,ra2,ra3;
            LDSM4(qa0,qa1,qa2,qa3, a0b + (uint32_t)(((2*ki+hi)^x0)<<4));
            LDSM4(ra0,ra1,ra2,ra3, a1b + (uint32_t)(((2*ki+hi)^x0)<<4));
            int krow = ki*16 + sel*8 + r7;
            uint32_t wr = smb + 65536u + (uint32_t)krow*512; int xw=krow&7;
            #pragma unroll
            for(int j=0;j<8;j++){
                int nt = h*16 + 2*j + nsel;
                uint32_t b0,b1,b2,b3;
                LDSM4T(b0,b1,b2,b3, wr + (uint32_t)((nt^xw)<<4));
                MMAH(acc[0][2*j],   qa0,qa1,qa2,qa3, b0,b1);
                MMAH(acc[0][2*j+1], qa0,qa1,qa2,qa3, b2,b3);
                MMAH(acc[1][2*j],   ra0,ra1,ra2,ra3, b0,b1);
                MMAH(acc[1][2*j+1], ra0,ra1,ra2,ra3, b2,b3);
            }
        }
        #pragma unroll
        for(int rt=0;rt<2;rt++){
            int rr = m0 + p*32 + rt*16 + g;
            #pragma unroll
            for(int n=0;n<16;n++){
                int col = h*128 + n*8 + 2*tig;
                float2 bb = *(const float2*)&bias[col];
                float v0=acc[rt][n][0]+bb.x, v1=acc[rt][n][1]+bb.y;
                float v2=acc[rt][n][2]+bb.x, v3=acc[rt][n][3]+bb.y;
                if(out32){
                    float2 y0=*(const float2*)&res[(size_t)rr*256+col];
                    float2 y1=*(const float2*)&res[(size_t)(rr+8)*256+col];
                    float2 w0={v0+y0.x,v1+y0.y}, w1={v2+y1.x,v3+y1.y};
                    *(float2*)&out32[(size_t)rr*256+col]=w0;
                    *(float2*)&out32[(size_t)(rr+8)*256+col]=w1;
                } else {
                    *(__half2*)(o16+(size_t)rr*256+col)     = __floats2half2_rn(v0,v1);
                    *(__half2*)(o16+(size_t)(rr+8)*256+col) = __floats2half2_rn(v2,v3);
                }
            }
        }
    };

    stageA(A1); stageW(W1); CPC(); CPW0(); __syncthreads();
    compute(b1, o1);
    if(W2){
        __syncthreads();
        stageA(A2); stageW(W2); CPC(); CPW0(); __syncthreads();
        compute(b2, o2);
        if(W3){
            __syncthreads();
            stageW(W3); CPC(); CPW0(); __syncthreads();
            compute(b3, o3);
        }
    }
}

// ---------------- fp16 mma flash attention, Bq=128, Bk=64, P-in-registers ----------------
// smem halfs: Q@0 (32768); K@32768 (2x16384); V@65536 (2x16384). 196608 B.
#define FK 32768
#define FV 65536
#define FL_BYTES 196608
__global__ void __launch_bounds__(256,1) flash_h(const __half* __restrict__ q,
        const __half* __restrict__ k, const __half* __restrict__ v, __half* __restrict__ o){
    extern __shared__ __half sh[];
    const uint32_t smb = smem_u32(sh);
    int tid=threadIdx.x, lane=tid&31, wid=tid>>5;
    int g=lane>>2, tig=lane&3;
    int b=blockIdx.y, qb=blockIdx.x;
    const __half* qg = q + ((size_t)b*SS + (size_t)qb*128)*CC;
    const __half* kg = k + (size_t)b*SS*CC;
    const __half* vg = v + (size_t)b*SS*CC;

    // stage Q + K0 + V0 (one group)
    #pragma unroll
    for(int i=0;i<16;i++){ int c=tid+i*256, r=c>>5, ch=c&31;
        CPAH(r*256 + ((ch^(r&7))<<3), qg + (size_t)c*8); }
    #pragma unroll
    for(int i=0;i<8;i++){ int c=tid+i*256, r=c>>5, ch=c&31;
        int sw = r*256 + ((ch^(r&7))<<3);
        CPAH(FK + sw, kg + (size_t)c*8);
        CPAH(FV + sw, vg + (size_t)c*8); }
    CPC();

    float acc[32][4];
    #pragma unroll
    for(int i=0;i<32;i++){ acc[i][0]=0.f;acc[i][1]=0.f;acc[i][2]=0.f;acc[i][3]=0.f; }
    float l0=0.f, l1=0.f;
    const int hi=(lane>>4)&1, sel=(lane>>3)&1, r7=lane&7, nsel=lane>>4;
    const int rq = wid*16 + (lane&7) + (lane&8); const int rq7 = rq&7;
    const uint32_t aqb = smb + (uint32_t)rq*512;
    const int kkey = (lane&7) + ((lane>>4)<<3);
    const int kcs  = (lane>>3)&1;

    int buf=0;
    for(int t=0;t<64;t++){
        CPW0();
        __syncthreads();     // data(buf) visible to all + everyone done reading buf^1
        if(t<63){
            const __half* kt = kg + (size_t)(t+1)*16384;
            const __half* vt = vg + (size_t)(t+1)*16384;
            int bo = (buf^1)*16384;
            #pragma unroll
            for(int i=0;i<8;i++){ int c=tid+i*256, r=c>>5, ch=c&31;
                int sw = r*256 + ((ch^(r&7))<<3);
                CPAH(FK + bo + sw, kt + (size_t)c*8);
                CPAH(FV + bo + sw, vt + (size_t)c*8); }
            CPC();
        }
        uint32_t kbb = smb + (uint32_t)(FK + buf*16384)*2;
        uint32_t vbb = smb + (uint32_t)(FV + buf*16384)*2;
        float s[8][4];
        #pragma unroll
        for(int n=0;n<8;n++){ s[n][0]=0.f;s[n][1]=0.f;s[n][2]=0.f;s[n][3]=0.f; }
        #pragma unroll
        for(int ki=0;ki<16;ki++){
            uint32_t a0,a1,a2,a3;
            LDSM4(a0,a1,a2,a3, aqb + (uint32_t)(((2*ki+hi)^rq7)<<4));
            #pragma unroll
            for(int G=0;G<4;G++){
                int row = G*16 + kkey;
                uint32_t b0,b1,b2,b3;
                LDSM4(b0,b1,b2,b3, kbb + (uint32_t)row*512 + (uint32_t)(((2*ki+kcs)^(row&7))<<4));
                MMAH(s[2*G],   a0,a1,a2,a3, b0,b1);
                MMAH(s[2*G+1], a0,a1,a2,a3, b2,b3);
            }
        }
        const float C2 = 0.09016994f;  // log2(e)/16
        #pragma unroll
        for(int kp=0;kp<4;kp++){
            uint32_t pa0,pa1,pa2,pa3;
            {
                int n=2*kp;
                uint32_t e0,e1;
                __half2 h0 = __floats2half2_rn(s[n][0]*C2, s[n][1]*C2);
                __half2 h1 = __floats2half2_rn(s[n][2]*C2, s[n][3]*C2);
                asm("ex2.approx.f16x2 %0, %1;":"=r"(e0):"r"(h2u(h0)));
                asm("ex2.approx.f16x2 %0, %1;":"=r"(e1):"r"(h2u(h1)));
                pa0=e0; pa1=e1;
                float2 f0=__half22float2(*(__half2*)&e0), f1=__half22float2(*(__half2*)&e1);
                l0 += f0.x+f0.y; l1 += f1.x+f1.y;
                n=2*kp+1;
                h0 = __floats2half2_rn(s[n][0]*C2, s[n][1]*C2);
                h1 = __floats2half2_rn(s[n][2]*C2, s[n][3]*C2);
                asm("ex2.approx.f16x2 %0, %1;":"=r"(e0):"r"(h2u(h0)));
                asm("ex2.approx.f16x2 %0, %1;":"=r"(e1):"r"(h2u(h1)));
                pa2=e0; pa3=e1;
                f0=__half22float2(*(__half2*)&e0); f1=__half22float2(*(__half2*)&e1);
                l0 += f0.x+f0.y; l1 += f1.x+f1.y;
            }
            int krow = kp*16 + sel*8 + r7;
            uint32_t vr = vbb + (uint32_t)krow*512; int xv=krow&7;
            #pragma unroll
            for(int j=0;j<16;j++){
                int nt = 2*j + nsel;
                uint32_t b0,b1,b2,b3;
                LDSM4T(b0,b1,b2,b3, vr + (uint32_t)((nt^xv)<<4));
                MMAH(acc[2*j],   pa0,pa1,pa2,pa3, b0,b1);
                MMAH(acc[2*j+1], pa0,pa1,pa2,pa3, b2,b3);
            }
        }
        buf ^= 1;
    }
    l0 += __shfl_xor_sync(~0u,l0,1); l0 += __shfl_xor_sync(~0u,l0,2);
    l1 += __shfl_xor_sync(~0u,l1,1); l1 += __shfl_xor_sync(~0u,l1,2);
    float inv0 = 1.f/l0, inv1 = 1.f/l1;
    __half* o0 = o + ((size_t)b*SS + (size_t)qb*128 + wid*16 + g)*CC;
    __half* o1 = o0 + 8*CC;
    #pragma unroll
    for(int n=0;n<32;n++){
        int col = n*8 + 2*tig;
        *(__half2*)(o0+col) = __floats2half2_rn(acc[n][0]*inv0, acc[n][1]*inv0);
        *(__half2*)(o1+col) = __floats2half2_rn(acc[n][2]*inv1, acc[n][3]*inv1);
    }
}

// ---------------- launcher ----------------
extern "C" void kernel_launch(void* const* d_in, const int* in_sizes, int n_in,
                              void* d_out, int out_size){
    const float* inputs  = (const float*)d_in[0];
    const float* context = (const float*)d_in[1];
    const float* Wq=(const float*)d_in[2];  const float* bq=(const float*)d_in[3];
    const float* Wk=(const float*)d_in[4];  const float* bk=(const float*)d_in[5];
    const float* Wv=(const float*)d_in[6];  const float* bv=(const float*)d_in[7];
    const float* Wp=(const float*)d_in[8];  const float* bp=(const float*)d_in[9];
    const float* gamma=(const float*)d_in[10]; const float* beta=(const float*)d_in[11];
    float* out=(float*)d_out;
    float *xn; __half *xn16,*ct16,*q16,*k16,*v16,*o16,*wq16,*wk16,*wv16,*wp16;
    cudaGetSymbolAddress((void**)&xn,g_xn);
    cudaGetSymbolAddress((void**)&xn16,g_xn16); cudaGetSymbolAddress((void**)&ct16,g_ct16);
    cudaGetSymbolAddress((void**)&q16,g_q16);   cudaGetSymbolAddress((void**)&k16,g_k16);
    cudaGetSymbolAddress((void**)&v16,g_v16);   cudaGetSymbolAddress((void**)&o16,g_o16);
    cudaGetSymbolAddress((void**)&wq16,g_wq16); cudaGetSymbolAddress((void**)&wk16,g_wk16);
    cudaGetSymbolAddress((void**)&wv16,g_wv16); cudaGetSymbolAddress((void**)&wp16,g_wp16);
    cudaFuncSetAttribute(flash_h, cudaFuncAttributeMaxDynamicSharedMemorySize, FL_BYTES);
    cudaFuncSetAttribute(gemm_h,  cudaFuncAttributeMaxDynamicSharedMemorySize, G_BYTES);

    ln_kernel<<<M_TOT/8,256>>>(inputs,gamma,beta,xn,xn16);
    cvt_all<<<2176,256>>>(context, ct16, Wq,Wk,Wv,Wp, wq16,wk16,wv16,wp16);
    gemm_h<<<M_TOT/128,256,G_BYTES>>>(xn16, wq16,bq,q16,
                                      ct16, wk16,bk,k16,
                                      wv16,bv,v16, nullptr,nullptr);
    flash_h<<<dim3(SS/128, BN), 256, FL_BYTES>>>(q16,k16,v16,o16);
    gemm_h<<<M_TOT/128,256,G_BYTES>>>(o16, wp16,bp,nullptr,
                                      nullptr, nullptr,nullptr,nullptr,
                                      nullptr,nullptr,nullptr, xn, out);
}

// round 10
// speedup vs baseline: 10.2365x; 1.0063x over previous
#include <cuda_runtime.h>
#include <cuda_fp16.h>
#include <math.h>
#include <stdint.h>

#define BN 4
#define SS 4096
#define CC 256
#define M_TOT (BN*SS)

__device__ float  g_xn  [(size_t)BN*SS*CC];
__device__ __half g_xn16[(size_t)BN*SS*CC];
__device__ __half g_ct16[(size_t)BN*SS*CC];
__device__ __half g_q16 [(size_t)BN*SS*CC];
__device__ __half g_k16 [(size_t)BN*SS*CC];
__device__ __half g_v16 [(size_t)BN*SS*CC];
__device__ __half g_o16 [(size_t)BN*SS*CC];
__device__ __half g_wq16[CC*CC];
__device__ __half g_wk16[CC*CC];
__device__ __half g_wv16[CC*CC];
__device__ __half g_wp16[CC*CC];

__device__ __forceinline__ uint32_t smem_u32(const void* p){
    uint32_t a; asm("{ .reg .u64 t; cvta.to.shared.u64 t, %1; cvt.u32.u64 %0, t; }":"=r"(a):"l"(p)); return a;
}
// plain asm: nvcc may interleave with loads for better ILP
#define MMAH(d,a0,a1,a2,a3,b0,b1) \
    asm("mma.sync.aligned.m16n8k16.row.col.f32.f16.f16.f32 {%0,%1,%2,%3},{%4,%5,%6,%7},{%8,%9},{%0,%1,%2,%3};" \
        :"+f"(d[0]),"+f"(d[1]),"+f"(d[2]),"+f"(d[3]) \
        :"r"(a0),"r"(a1),"r"(a2),"r"(a3),"r"(b0),"r"(b1))
#define LDSM4(r0,r1,r2,r3,a) asm volatile("ldmatrix.sync.aligned.m8n8.x4.shared.b16 {%0,%1,%2,%3},[%4];" \
        :"=r"(r0),"=r"(r1),"=r"(r2),"=r"(r3):"r"(a))
#define LDSM4T(r0,r1,r2,r3,a) asm volatile("ldmatrix.sync.aligned.m8n8.x4.trans.shared.b16 {%0,%1,%2,%3},[%4];" \
        :"=r"(r0),"=r"(r1),"=r"(r2),"=r"(r3):"r"(a))
#define CPAH(off_h, src) asm volatile("cp.async.cg.shared.global [%0], [%1], 16;"::"r"(smb+(uint32_t)((off_h)*2)),"l"(src):"memory")
#define CPC()  asm volatile("cp.async.commit_group;":::"memory")
#define CPW0() asm volatile("cp.async.wait_group 0;":::"memory")
__device__ __forceinline__ uint32_t h2u(__half2 x){ return *(uint32_t*)&x; }

// ---------------- LayerNorm: warp/row, dual fp32+fp16 out ----------------
__global__ void ln_kernel(const float* __restrict__ x, const float* __restrict__ gamma,
                          const float* __restrict__ beta, float* __restrict__ out32,
                          __half* __restrict__ out16){
    int wid = threadIdx.x>>5, lane = threadIdx.x&31;
    size_t row = (size_t)blockIdx.x*8 + wid;
    const float* xr = x + row*CC + lane*8;
    float4 v0 = *(const float4*)xr, v1 = *(const float4*)(xr+4);
    float s = v0.x+v0.y+v0.z+v0.w+v1.x+v1.y+v1.z+v1.w;
    #pragma unroll
    for(int o=16;o;o>>=1) s += __shfl_xor_sync(~0u,s,o);
    float mu = s*(1.f/CC);
    v0.x-=mu;v0.y-=mu;v0.z-=mu;v0.w-=mu;v1.x-=mu;v1.y-=mu;v1.z-=mu;v1.w-=mu;
    float q = v0.x*v0.x+v0.y*v0.y+v0.z*v0.z+v0.w*v0.w+v1.x*v1.x+v1.y*v1.y+v1.z*v1.z+v1.w*v1.w;
    #pragma unroll
    for(int o=16;o;o>>=1) q += __shfl_xor_sync(~0u,q,o);
    float rs = rsqrtf(q*(1.f/CC)+1e-3f);
    const float4 ga0 = *(const float4*)(gamma+lane*8), ga1 = *(const float4*)(gamma+lane*8+4);
    const float4 be0 = *(const float4*)(beta +lane*8), be1 = *(const float4*)(beta +lane*8+4);
    float4 o0,o1;
    o0.x=v0.x*rs*ga0.x+be0.x; o0.y=v0.y*rs*ga0.y+be0.y; o0.z=v0.z*rs*ga0.z+be0.z; o0.w=v0.w*rs*ga0.w+be0.w;
    o1.x=v1.x*rs*ga1.x+be1.x; o1.y=v1.y*rs*ga1.y+be1.y; o1.z=v1.z*rs*ga1.z+be1.z; o1.w=v1.w*rs*ga1.w+be1.w;
    float* op = out32 + row*CC + lane*8;
    *(float4*)op = o0; *(float4*)(op+4) = o1;
    uint4 hp = make_uint4(h2u(__floats2half2_rn(o0.x,o0.y)), h2u(__floats2half2_rn(o0.z,o0.w)),
                          h2u(__floats2half2_rn(o1.x,o1.y)), h2u(__floats2half2_rn(o1.z,o1.w)));
    *(uint4*)(out16 + row*CC + lane*8) = hp;
}

// ---------------- fused fp32->fp16 convert: context + 4 weights ----------------
__global__ void cvt_all(const float* __restrict__ ctx, __half* __restrict__ dctx,
        const float* __restrict__ Wq, const float* __restrict__ Wk,
        const float* __restrict__ Wv, const float* __restrict__ Wp,
        __half* __restrict__ dwq, __half* __restrict__ dwk,
        __half* __restrict__ dwv, __half* __restrict__ dwp){
    int blk = blockIdx.x;
    const float* src; __half* dst; size_t base;
    if(blk < 2048){ src=ctx; dst=dctx; base=(size_t)blk*2048; }
    else{
        int w=(blk-2048)>>5, off=(blk-2048)&31;
        src = w==0?Wq : w==1?Wk : w==2?Wv : Wp;
        dst = w==0?dwq: w==1?dwk: w==2?dwv: dwp;
        base = (size_t)off*2048;
    }
    size_t i = base + (size_t)threadIdx.x*8;
    float4 a=*(const float4*)(src+i), b=*(const float4*)(src+i+4);
    uint4 r = make_uint4(h2u(__floats2half2_rn(a.x,a.y)),h2u(__floats2half2_rn(a.z,a.w)),
                         h2u(__floats2half2_rn(b.x,b.y)),h2u(__floats2half2_rn(b.z,b.w)));
    *(uint4*)(dst+i)=r;
}

// ---------------- fp16 mma GEMM, up to 3 passes, split-K W pipelining ----------------
// smem halfs: A[128][256] @0 (64KB); W half0 @32768 (64KB); W half1 @65536 (64KB).
#define GW 32768
#define G_BYTES 196608
__global__ void __launch_bounds__(256,1) gemm_h(
        const __half* __restrict__ A1, const __half* __restrict__ W1, const float* __restrict__ b1, float s1, __half* __restrict__ o1,
        const __half* __restrict__ A2, const __half* __restrict__ W2, const float* __restrict__ b2, __half* __restrict__ o2,
        const __half* __restrict__ W3, const float* __restrict__ b3, __half* __restrict__ o3,
        const float* __restrict__ res, float* __restrict__ out32){
    extern __shared__ __half sh[];
    const uint32_t smb = smem_u32(sh);
    int tid=threadIdx.x, lane=tid&31, wid=tid>>5;
    int g=lane>>2, tig=lane&3, p=wid>>1, h=wid&1;
    int m0 = blockIdx.x*128;
    const int ria=(lane&7)+(lane&8), hi=(lane>>4)&1, sel=(lane>>3)&1, r7=lane&7, nsel=lane>>4;

    auto stageA = [&](const __half* A){
        #pragma unroll
        for(int i=0;i<16;i++){ int c=tid+i*256, r=c>>5, ch=c&31;
            CPAH(r*256 + ((ch^(r&7))<<3), A + (size_t)(m0+r)*256 + ch*8); }
    };
    // stage 128 k-rows of W into slot (0/1)
    auto stageWh = [&](const __half* W, int half, int slot){
        #pragma unroll
        for(int i=0;i<16;i++){ int c=tid+i*256, kr=c>>5, ch=c&31;
            CPAH(GW + slot*32768 + kr*256 + ((ch^(kr&7))<<3),
                 W + (size_t)(half*128+kr)*256 + ch*8); }
    };

    float acc[2][16][4];
    int row0 = p*32 + ria, row1 = row0 + 16;
    uint32_t a0b = smb + (uint32_t)row0*512, a1b = smb + (uint32_t)row1*512;
    int x0 = row0&7;

    auto compute_half = [&](int kh){
        #pragma unroll
        for(int kl=0;kl<8;kl++){
            int ki = kh*8 + kl;
            uint32_t qa0,qa1,qa2,qa3, ra0,ra1,ra2,ra3;
            LDSM4(qa0,qa1,qa2,qa3, a0b + (uint32_t)(((2*ki+hi)^x0)<<4));
            LDSM4(ra0,ra1,ra2,ra3, a1b + (uint32_t)(((2*ki+hi)^x0)<<4));
            int lrow = kl*16 + sel*8 + r7;
            uint32_t wr = smb + (uint32_t)(GW + kh*32768)*2 + (uint32_t)lrow*512; int xw=lrow&7;
            #pragma unroll
            for(int j=0;j<8;j++){
                int nt = h*16 + 2*j + nsel;
                uint32_t b0,b1,b2,b3;
                LDSM4T(b0,b1,b2,b3, wr + (uint32_t)((nt^xw)<<4));
                MMAH(acc[0][2*j],   qa0,qa1,qa2,qa3, b0,b1);
                MMAH(acc[0][2*j+1], qa0,qa1,qa2,qa3, b2,b3);
                MMAH(acc[1][2*j],   ra0,ra1,ra2,ra3, b0,b1);
                MMAH(acc[1][2*j+1], ra0,ra1,ra2,ra3, b2,b3);
            }
        }
    };
    auto epilogue = [&](const float* bias, float osc, __half* o16){
        #pragma unroll
        for(int rt=0;rt<2;rt++){
            int rr = m0 + p*32 + rt*16 + g;
            #pragma unroll
            for(int n=0;n<16;n++){
                int col = h*128 + n*8 + 2*tig;
                float2 bb = *(const float2*)&bias[col];
                float v0=acc[rt][n][0]+bb.x, v1=acc[rt][n][1]+bb.y;
                float v2=acc[rt][n][2]+bb.x, v3=acc[rt][n][3]+bb.y;
                if(out32){
                    float2 y0=*(const float2*)&res[(size_t)rr*256+col];
                    float2 y1=*(const float2*)&res[(size_t)(rr+8)*256+col];
                    float2 w0={v0+y0.x,v1+y0.y}, w1={v2+y1.x,v3+y1.y};
                    *(float2*)&out32[(size_t)rr*256+col]=w0;
                    *(float2*)&out32[(size_t)(rr+8)*256+col]=w1;
                } else {
                    *(__half2*)(o16+(size_t)rr*256+col)     = __floats2half2_rn(v0*osc,v1*osc);
                    *(__half2*)(o16+(size_t)(rr+8)*256+col) = __floats2half2_rn(v2*osc,v3*osc);
                }
            }
        }
    };
    auto zacc = [&](){
        #pragma unroll
        for(int rt=0;rt<2;rt++) for(int n=0;n<16;n++){ acc[rt][n][0]=0.f;acc[rt][n][1]=0.f;acc[rt][n][2]=0.f;acc[rt][n][3]=0.f; }
    };

    // pass 1
    stageA(A1); stageWh(W1,0,0); CPC(); CPW0(); __syncthreads();
    stageWh(W1,1,1); CPC();
    zacc(); compute_half(0);
    CPW0(); __syncthreads();          // half1 ready; slot0 free
    compute_half(1);
    epilogue(b1, s1, o1);
    if(W2){
        __syncthreads();              // all done reading A1/slot1
        stageA(A2); stageWh(W2,0,0); CPC(); CPW0(); __syncthreads();
        stageWh(W2,1,1); CPC();
        zacc(); compute_half(0);
        CPW0(); __syncthreads();      // slot0 free now
        if(W3){ stageWh(W3,0,0); CPC(); }   // overlap next half0 with compute (A unchanged)
        compute_half(1);
        epilogue(b2, 1.f, o2);
        if(W3){
            CPW0(); __syncthreads();
            stageWh(W3,1,1); CPC();
            zacc(); compute_half(0);
            CPW0(); __syncthreads();
            compute_half(1);
            epilogue(b3, 1.f, o3);
        }
    }
}

// ---------------- fp16 mma flash attention, Bq=128, Bk=64, P-in-registers ----------------
// Q is pre-scaled by log2(e)/16 => exp2 of raw scores, no FMULs.
#define FK 32768
#define FV 65536
#define FL_BYTES 196608
__global__ void __launch_bounds__(256,1) flash_h(const __half* __restrict__ q,
        const __half* __restrict__ k, const __half* __restrict__ v, __half* __restrict__ o){
    extern __shared__ __half sh[];
    const uint32_t smb = smem_u32(sh);
    int tid=threadIdx.x, lane=tid&31, wid=tid>>5;
    int g=lane>>2, tig=lane&3;
    int b=blockIdx.y, qb=blockIdx.x;
    const __half* qg = q + ((size_t)b*SS + (size_t)qb*128)*CC;
    const __half* kg = k + (size_t)b*SS*CC;
    const __half* vg = v + (size_t)b*SS*CC;

    #pragma unroll
    for(int i=0;i<16;i++){ int c=tid+i*256, r=c>>5, ch=c&31;
        CPAH(r*256 + ((ch^(r&7))<<3), qg + (size_t)c*8); }
    #pragma unroll
    for(int i=0;i<8;i++){ int c=tid+i*256, r=c>>5, ch=c&31;
        int sw = r*256 + ((ch^(r&7))<<3);
        CPAH(FK + sw, kg + (size_t)c*8);
        CPAH(FV + sw, vg + (size_t)c*8); }
    CPC();

    float acc[32][4];
    #pragma unroll
    for(int i=0;i<32;i++){ acc[i][0]=0.f;acc[i][1]=0.f;acc[i][2]=0.f;acc[i][3]=0.f; }
    float l0=0.f, l1=0.f;
    const int hi=(lane>>4)&1, sel=(lane>>3)&1, r7=lane&7, nsel=lane>>4;
    const int rq = wid*16 + (lane&7) + (lane&8); const int rq7 = rq&7;
    const uint32_t aqb = smb + (uint32_t)rq*512;
    const int kkey = (lane&7) + ((lane>>4)<<3);
    const int kcs  = (lane>>3)&1;

    int buf=0;
    for(int t=0;t<64;t++){
        CPW0();
        __syncthreads();
        if(t<63){
            const __half* kt = kg + (size_t)(t+1)*16384;
            const __half* vt = vg + (size_t)(t+1)*16384;
            int bo = (buf^1)*16384;
            #pragma unroll
            for(int i=0;i<8;i++){ int c=tid+i*256, r=c>>5, ch=c&31;
                int sw = r*256 + ((ch^(r&7))<<3);
                CPAH(FK + bo + sw, kt + (size_t)c*8);
                CPAH(FV + bo + sw, vt + (size_t)c*8); }
            CPC();
        }
        uint32_t kbb = smb + (uint32_t)(FK + buf*16384)*2;
        uint32_t vbb = smb + (uint32_t)(FV + buf*16384)*2;
        float s[8][4];
        #pragma unroll
        for(int n=0;n<8;n++){ s[n][0]=0.f;s[n][1]=0.f;s[n][2]=0.f;s[n][3]=0.f; }
        #pragma unroll
        for(int ki=0;ki<16;ki++){
            uint32_t a0,a1,a2,a3;
            LDSM4(a0,a1,a2,a3, aqb + (uint32_t)(((2*ki+hi)^rq7)<<4));
            #pragma unroll
            for(int G=0;G<4;G++){
                int row = G*16 + kkey;
                uint32_t b0,b1,b2,b3;
                LDSM4(b0,b1,b2,b3, kbb + (uint32_t)row*512 + (uint32_t)(((2*ki+kcs)^(row&7))<<4));
                MMAH(s[2*G],   a0,a1,a2,a3, b0,b1);
                MMAH(s[2*G+1], a0,a1,a2,a3, b2,b3);
            }
        }
        #pragma unroll
        for(int kp=0;kp<4;kp++){
            uint32_t pa0,pa1,pa2,pa3;
            {
                int n=2*kp;
                uint32_t e0,e1;
                __half2 h0 = __floats2half2_rn(s[n][0], s[n][1]);
                __half2 h1 = __floats2half2_rn(s[n][2], s[n][3]);
                asm("ex2.approx.f16x2 %0, %1;":"=r"(e0):"r"(h2u(h0)));
                asm("ex2.approx.f16x2 %0, %1;":"=r"(e1):"r"(h2u(h1)));
                pa0=e0; pa1=e1;
                float2 f0=__half22float2(*(__half2*)&e0), f1=__half22float2(*(__half2*)&e1);
                l0 += f0.x+f0.y; l1 += f1.x+f1.y;
                n=2*kp+1;
                h0 = __floats2half2_rn(s[n][0], s[n][1]);
                h1 = __floats2half2_rn(s[n][2], s[n][3]);
                asm("ex2.approx.f16x2 %0, %1;":"=r"(e0):"r"(h2u(h0)));
                asm("ex2.approx.f16x2 %0, %1;":"=r"(e1):"r"(h2u(h1)));
                pa2=e0; pa3=e1;
                f0=__half22float2(*(__half2*)&e0); f1=__half22float2(*(__half2*)&e1);
                l0 += f0.x+f0.y; l1 += f1.x+f1.y;
            }
            int krow = kp*16 + sel*8 + r7;
            uint32_t vr = vbb + (uint32_t)krow*512; int xv=krow&7;
            #pragma unroll
            for(int j=0;j<16;j++){
                int nt = 2*j + nsel;
                uint32_t b0,b1,b2,b3;
                LDSM4T(b0,b1,b2,b3, vr + (uint32_t)((nt^xv)<<4));
                MMAH(acc[2*j],   pa0,pa1,pa2,pa3, b0,b1);
                MMAH(acc[2*j+1], pa0,pa1,pa2,pa3, b2,b3);
            }
        }
        buf ^= 1;
    }
    l0 += __shfl_xor_sync(~0u,l0,1); l0 += __shfl_xor_sync(~0u,l0,2);
    l1 += __shfl_xor_sync(~0u,l1,1); l1 += __shfl_xor_sync(~0u,l1,2);
    float inv0 = 1.f/l0, inv1 = 1.f/l1;
    __half* o0 = o + ((size_t)b*SS + (size_t)qb*128 + wid*16 + g)*CC;
    __half* o1 = o0 + 8*CC;
    #pragma unroll
    for(int n=0;n<32;n++){
        int col = n*8 + 2*tig;
        *(__half2*)(o0+col) = __floats2half2_rn(acc[n][0]*inv0, acc[n][1]*inv0);
        *(__half2*)(o1+col) = __floats2half2_rn(acc[n][2]*inv1, acc[n][3]*inv1);
    }
}

// ---------------- launcher ----------------
extern "C" void kernel_launch(void* const* d_in, const int* in_sizes, int n_in,
                              void* d_out, int out_size){
    const float* inputs  = (const float*)d_in[0];
    const float* context = (const float*)d_in[1];
    const float* Wq=(const float*)d_in[2];  const float* bq=(const float*)d_in[3];
    const float* Wk=(const float*)d_in[4];  const float* bk=(const float*)d_in[5];
    const float* Wv=(const float*)d_in[6];  const float* bv=(const float*)d_in[7];
    const float* Wp=(const float*)d_in[8];  const float* bp=(const float*)d_in[9];
    const float* gamma=(const float*)d_in[10]; const float* beta=(const float*)d_in[11];
    float* out=(float*)d_out;
    float *xn; __half *xn16,*ct16,*q16,*k16,*v16,*o16,*wq16,*wk16,*wv16,*wp16;
    cudaGetSymbolAddress((void**)&xn,g_xn);
    cudaGetSymbolAddress((void**)&xn16,g_xn16); cudaGetSymbolAddress((void**)&ct16,g_ct16);
    cudaGetSymbolAddress((void**)&q16,g_q16);   cudaGetSymbolAddress((void**)&k16,g_k16);
    cudaGetSymbolAddress((void**)&v16,g_v16);   cudaGetSymbolAddress((void**)&o16,g_o16);
    cudaGetSymbolAddress((void**)&wq16,g_wq16); cudaGetSymbolAddress((void**)&wk16,g_wk16);
    cudaGetSymbolAddress((void**)&wv16,g_wv16); cudaGetSymbolAddress((void**)&wp16,g_wp16);
    cudaFuncSetAttribute(flash_h, cudaFuncAttributeMaxDynamicSharedMemorySize, FL_BYTES);
    cudaFuncSetAttribute(gemm_h,  cudaFuncAttributeMaxDynamicSharedMemorySize, G_BYTES);

    const float QSC = 0.09016994f;   // log2(e)/16: folded softmax scale
    ln_kernel<<<M_TOT/8,256>>>(inputs,gamma,beta,xn,xn16);
    cvt_all<<<2176,256>>>(context, ct16, Wq,Wk,Wv,Wp, wq16,wk16,wv16,wp16);
    gemm_h<<<M_TOT/128,256,G_BYTES>>>(xn16, wq16,bq,QSC,q16,
                                      ct16, wk16,bk,k16,
                                      wv16,bv,v16, nullptr,nullptr);
    flash_h<<<dim3(SS/128, BN), 256, FL_BYTES>>>(q16,k16,v16,o16);
    gemm_h<<<M_TOT/128,256,G_BYTES>>>(o16, wp16,bp,1.f,nullptr,
                                      nullptr, nullptr,nullptr,nullptr,
                                      nullptr,nullptr,nullptr, xn, out);
}